// round 1
// baseline (speedup 1.0000x reference)
#include <cuda_runtime.h>
#include <math.h>
#include <stdint.h>

// Problem constants
#define BB 8
#define SS 4096
#define SEQQ 16
#define ICC 704
#define TT 4
#define LL 3
#define H1C 768
#define H2C 1280

// out layout (floats)
#define OUT0_ELEMS (8L*4096L*768L)       // 25165824
#define OUT1_ELEMS (8L*4096L*1280L)      // 41943040
#define OUT2_ELEMS (8L*2816L)            // 22528

// float4 copy ranges
static constexpr long N40 = OUT0_ELEMS / 4;            // 6291456
static constexpr long N41 = OUT1_ELEMS / 4;            // 10485760
static constexpr long N42 = OUT2_ELEMS / 4;            // 5632
static constexpr long N4T = N40 + N41 + N42;           // 16782848

static constexpr int NCOMP = 128;   // compute CTAs per stage
static constexpr int NCOPY = 192;   // copy CTAs per stage
static constexpr int NGRID = NCOMP + NCOPY;

// scratch: chains 0..3 = te1 (hid 768), 4..7 = te2 (hid 1280)
// per-chain h buffer: 128 rows x hid
__device__ float g_bufA[1048576];   // 4 MB
__device__ float g_bufB[1048576];
__device__ int   g_npos[8];

__device__ __forceinline__ size_t ch_off(int c) {
    return (c < 4) ? (size_t)c * 128 * 768
                   : (size_t)4 * 128 * 768 + (size_t)(c - 4) * 128 * 1280;
}

struct Params {
    const float* extra;
    const float* f1w[2]; const float* f1b[2];
    const float* gg[2];  const float* gb[2];
    const float* bw[2];  const float* bb[2];
    const float* ow[2];  const float* ob[2];
    const float* e0; const float* e1; const float* e2;
    float* out;
};

// ---------------- npos: count rows with nonzero tail-256 channels ----------------
__global__ void npos_kernel(const float* __restrict__ extra) {
    __shared__ float red[256];
    int b = blockIdx.x, tid = threadIdx.x;
    int cnt = 0;
    for (int s = 0; s < SEQQ; s++) {
        float v = fabsf(extra[((size_t)b * SEQQ + s) * ICC + 448 + tid]);
        red[tid] = v;
        __syncthreads();
        for (int o = 128; o > 0; o >>= 1) {
            if (tid < o) red[tid] += red[tid + o];
            __syncthreads();
        }
        if (tid == 0 && red[0] > 1e-6f) cnt++;
        __syncthreads();
    }
    if (tid == 0) g_npos[b] = cnt;
}

// ---------------- fused stage kernel: GEMM (+GN, silu, residual) + copy slice ----------------
// MODE 0: h = silu(extra @ fc1_w^T + b)          K=704
// MODE 1: h = h + silu(GN(h) @ blk_w^T + b)      K=hid
// MODE 2: tok = h @ out_w^T + b                  K=hid
// ab: 0 => in=bufA, out=bufB ; 1 => in=bufB, out=bufA
template <int MODE>
__global__ void __launch_bounds__(256) stage_kernel(Params p, int layer, int slice, int ab) {
    int cid = blockIdx.x;

    if (cid >= NCOMP) {
        // ---- overlapped copy slice ----
        const float4* e0 = (const float4*)p.e0;
        const float4* e1 = (const float4*)p.e1;
        const float4* e2 = (const float4*)p.e2;
        float4* o4 = (float4*)p.out;
        long start = (long)slice * N4T / 5;
        long end   = (long)(slice + 1) * N4T / 5;
        for (long idx = start + (long)(cid - NCOMP) * 256 + threadIdx.x;
             idx < end; idx += (long)NCOPY * 256) {
            float4 v;
            if (idx < N40)            v = e0[idx];
            else if (idx < N40 + N41) v = e1[idx - N40];
            else                      v = e2[idx - N40 - N41];
            o4[idx] = v;
        }
        return;
    }

    // ---- decode compute CTA ----
    int chain, mt, nt, hid;
    if (cid < 48) { chain = cid / 12; int r = cid % 12; mt = r / 6; nt = r % 6; hid = 768; }
    else { int c = cid - 48; chain = 4 + c / 20; int r = c % 20; mt = r / 10; nt = r % 10; hid = 1280; }
    int te = chain >> 2, t = chain & 3;
    int K = (MODE == 0) ? ICC : hid;

    const float* h_in  = ab ? g_bufB : g_bufA;
    float*       h_out = ab ? g_bufA : g_bufB;
    const float* A = (MODE == 0) ? p.extra : h_in + ch_off(chain);
    float*       O = h_out + ch_off(chain);

    const float* W; const float* bias;
    const float* gng = nullptr; const float* gnb = nullptr;
    if (MODE == 0) {
        W = p.f1w[te] + (size_t)t * hid * ICC;
        bias = p.f1b[te] + t * hid;
    } else if (MODE == 1) {
        W = p.bw[te] + (size_t)(t * LL + layer) * hid * hid;
        bias = p.bb[te] + (size_t)(t * LL + layer) * hid;
        gng = p.gg[te] + (size_t)(t * LL + layer) * hid;
        gnb = p.gb[te] + (size_t)(t * LL + layer) * hid;
    } else {
        W = p.ow[te] + (size_t)t * hid * hid;
        bias = p.ob[te] + t * hid;
    }

    int m0 = mt * 64, n0 = nt * 128;
    int gs = hid >> 5;                       // 24 or 40
    int magic = (gs == 24) ? 2731 : 1639;    // k/gs == (k*magic)>>16, exact for k<1280

    __shared__ float As[16][64];
    __shared__ float Ws[16][128];
    __shared__ float s_mean[64][32];
    __shared__ float s_rstd[64][32];

    int tid = threadIdx.x;
    int trow = tid >> 4, tcol = tid & 15;
    int lm = tid >> 2, lk = (tid & 3) << 2;

    if (MODE == 1) {
        float inv_gs = 1.0f / (float)gs;
        for (int pi = tid; pi < 64 * 32; pi += 256) {
            int r = pi >> 5, g = pi & 31;
            const float* src = A + (size_t)(m0 + r) * K + g * gs;
            float s = 0.f, ss = 0.f;
            for (int j = 0; j < gs; j += 4) {
                float4 v = *(const float4*)(src + j);
                s  += v.x + v.y + v.z + v.w;
                ss += v.x * v.x + v.y * v.y + v.z * v.z + v.w * v.w;
            }
            float mean = s * inv_gs;
            float var = ss * inv_gs - mean * mean;
            s_mean[r][g] = mean;
            s_rstd[r][g] = rsqrtf(var + 1e-5f);
        }
        __syncthreads();
    }

    float acc[4][8];
    #pragma unroll
    for (int i = 0; i < 4; i++)
        #pragma unroll
        for (int j = 0; j < 8; j++) acc[i][j] = 0.f;

    for (int k0 = 0; k0 < K; k0 += 16) {
        __syncthreads();
        // A tile -> As[k][m], with GN applied for MODE==1
        {
            const float* ap = A + (size_t)(m0 + lm) * K + k0 + lk;
            float4 v = *(const float4*)ap;
            float vv[4] = {v.x, v.y, v.z, v.w};
            #pragma unroll
            for (int j = 0; j < 4; j++) {
                float x = vv[j];
                if (MODE == 1) {
                    int k = k0 + lk + j;
                    int g = (k * magic) >> 16;
                    x = (x - s_mean[lm][g]) * s_rstd[lm][g] * gng[k] + gnb[k];
                }
                As[lk + j][lm] = x;
            }
        }
        // W tile -> Ws[k][n]
        #pragma unroll
        for (int i = 0; i < 2; i++) {
            int n = lm + i * 64;
            const float4 w = *(const float4*)(W + (size_t)(n0 + n) * K + k0 + lk);
            Ws[lk + 0][n] = w.x; Ws[lk + 1][n] = w.y;
            Ws[lk + 2][n] = w.z; Ws[lk + 3][n] = w.w;
        }
        __syncthreads();
        #pragma unroll
        for (int kk = 0; kk < 16; kk++) {
            float4 a  = *(const float4*)&As[kk][trow * 4];
            float4 w0 = *(const float4*)&Ws[kk][tcol * 8];
            float4 w1 = *(const float4*)&Ws[kk][tcol * 8 + 4];
            float av[4] = {a.x, a.y, a.z, a.w};
            float wv[8] = {w0.x, w0.y, w0.z, w0.w, w1.x, w1.y, w1.z, w1.w};
            #pragma unroll
            for (int i = 0; i < 4; i++)
                #pragma unroll
                for (int j = 0; j < 8; j++)
                    acc[i][j] += av[i] * wv[j];
        }
    }
    __syncthreads();

    // epilogue
    #pragma unroll
    for (int i = 0; i < 4; i++) {
        int r = m0 + trow * 4 + i;
        #pragma unroll
        for (int j = 0; j < 8; j++) {
            int c = n0 + tcol * 8 + j;
            float v = acc[i][j] + bias[c];
            if (MODE <= 1) v = v / (1.f + expf(-v));   // silu
            if (MODE == 1) v += A[(size_t)r * K + c];  // residual (K==hid)
            O[(size_t)r * hid + c] = v;
        }
    }
}

// ---------------- scatter: final overwrite of token regions ----------------
// Region r in [0,3]: out[b, S-1-r*np-i] = tok[b, r, i]   (reversed)
// Region r == 4:     out[b, S-5*np+i]  = tok[b, 3, i]    (forward)
__global__ void scatter_kernel(float* __restrict__ out) {
    int b = blockIdx.x, r = blockIdx.y, te = blockIdx.z;
    int np = g_npos[b];
    if (np == 0) return;
    int hid = te ? H2C : H1C;
    int t = (r < 4) ? r : 3;
    int chain = te * 4 + t;
    const float* tok = g_bufA + ch_off(chain);
    float* o = te ? out + OUT0_ELEMS + (size_t)b * SS * H2C
                  : out + (size_t)b * SS * H1C;
    int h4 = hid >> 2;
    int tot = np * h4;
    for (int e = threadIdx.x; e < tot; e += blockDim.x) {
        int i = e / h4, c4 = e % h4;
        int s = (r < 4) ? (SS - 1 - r * np - i) : (SS - 5 * np + i);
        float4 v = ((const float4*)(tok + (size_t)(b * SEQQ + i) * hid))[c4];
        ((float4*)(o + (size_t)s * hid))[c4] = v;
    }
}

extern "C" void kernel_launch(void* const* d_in, const int* in_sizes, int n_in,
                              void* d_out, int out_size) {
    Params p;
    p.e0    = (const float*)d_in[0];
    p.e1    = (const float*)d_in[1];
    p.e2    = (const float*)d_in[2];
    p.extra = (const float*)d_in[3];
    p.f1w[0] = (const float*)d_in[4];  p.f1b[0] = (const float*)d_in[5];
    p.gg[0]  = (const float*)d_in[6];  p.gb[0]  = (const float*)d_in[7];
    p.bw[0]  = (const float*)d_in[8];  p.bb[0]  = (const float*)d_in[9];
    p.ow[0]  = (const float*)d_in[10]; p.ob[0]  = (const float*)d_in[11];
    p.f1w[1] = (const float*)d_in[12]; p.f1b[1] = (const float*)d_in[13];
    p.gg[1]  = (const float*)d_in[14]; p.gb[1]  = (const float*)d_in[15];
    p.bw[1]  = (const float*)d_in[16]; p.bb[1]  = (const float*)d_in[17];
    p.ow[1]  = (const float*)d_in[18]; p.ob[1]  = (const float*)d_in[19];
    p.out = (float*)d_out;

    npos_kernel<<<8, 256>>>(p.extra);

    // fc1 -> bufA
    stage_kernel<0><<<NGRID, 256>>>(p, 0, 0, /*ab=*/1);
    // blocks: A->B, B->A, A->B
    stage_kernel<1><<<NGRID, 256>>>(p, 0, 1, /*ab=*/0);
    stage_kernel<1><<<NGRID, 256>>>(p, 1, 2, /*ab=*/1);
    stage_kernel<1><<<NGRID, 256>>>(p, 2, 3, /*ab=*/0);
    // out: B -> A (final tokens in bufA)
    stage_kernel<2><<<NGRID, 256>>>(p, 0, 4, /*ab=*/1);

    scatter_kernel<<<dim3(8, 5, 2), 256>>>(p.out);
}

// round 3
// speedup vs baseline: 1.3969x; 1.3969x over previous
#include <cuda_runtime.h>
#include <cuda_bf16.h>
#include <math.h>
#include <stdint.h>

// ---------------- problem constants ----------------
#define SSV 4096
#define H1C 768
#define H2C 1280

static constexpr long OUT0_ELEMS = 8L * 4096L * 768L;
static constexpr long OUT1_ELEMS = 8L * 4096L * 1280L;
static constexpr long OUT2_ELEMS = 8L * 2816L;

static constexpr long N40 = OUT0_ELEMS / 4;
static constexpr long N41 = OUT1_ELEMS / 4;
static constexpr long N42 = OUT2_ELEMS / 4;
static constexpr long N4T = N40 + N41 + N42;

static constexpr int NCOMP = 128;    // compute CTAs: one 128x64 tile each
static constexpr int NCTA  = 148;
static constexpr int CHUNK4 = 16384; // float4 per copy ticket

// smem: two 48KB buffers + 1KB alignment slack
// buffer layout: Ah[128x64 bf16]=16K, Al=16K, Wh[64x64]=8K, Wl=8K
static constexpr int BUFB = 49152;
static constexpr int SMEM_BYTES = 1024 + 2 * BUFB;

// ---------------- device globals ----------------
__device__ float g_bufA[1048576];
__device__ float g_bufB[1048576];
__device__ float g_stats[65536];   // [chain*8192 + (rstd?4096:0) + row*32 + grp]
__device__ int   g_npos[8];
__device__ int   g_cnt[8];
__device__ int   g_ticket;

__device__ __forceinline__ size_t ch_off(int c) {
    return (c < 4) ? (size_t)c * 128 * 768
                   : (size_t)4 * 128 * 768 + (size_t)(c - 4) * 128 * 1280;
}

struct Params {
    const float* extra;
    const float* f1w[2]; const float* f1b[2];
    const float* gg[2];  const float* gb[2];
    const float* bw[2];  const float* bb[2];
    const float* ow[2];  const float* ob[2];
    const float* e0; const float* e1; const float* e2;
    float* out;
};

// ---------------- helpers ----------------
__device__ __forceinline__ uint32_t s2u(const void* p) {
    uint32_t a;
    asm("{ .reg .u64 t; cvta.to.shared.u64 t, %1; cvt.u32.u64 %0, t; }" : "=r"(a) : "l"(p));
    return a;
}
__device__ __forceinline__ uint32_t swz(uint32_t o) { return o ^ ((o >> 3) & 0x70); }

__device__ __forceinline__ void ldsm4(uint32_t* r, uint32_t a) {
    asm volatile("ldmatrix.sync.aligned.m8n8.x4.shared.b16 {%0,%1,%2,%3}, [%4];"
                 : "=r"(r[0]), "=r"(r[1]), "=r"(r[2]), "=r"(r[3]) : "r"(a));
}
__device__ __forceinline__ void ldsm2(uint32_t* r, uint32_t a) {
    asm volatile("ldmatrix.sync.aligned.m8n8.x2.shared.b16 {%0,%1}, [%2];"
                 : "=r"(r[0]), "=r"(r[1]) : "r"(a));
}
__device__ __forceinline__ void mma16816(float* d, const uint32_t* a, const uint32_t* b) {
    asm volatile(
        "mma.sync.aligned.m16n8k16.row.col.f32.bf16.bf16.f32 "
        "{%0,%1,%2,%3}, {%4,%5,%6,%7}, {%8,%9}, {%0,%1,%2,%3};"
        : "+f"(d[0]), "+f"(d[1]), "+f"(d[2]), "+f"(d[3])
        : "r"(a[0]), "r"(a[1]), "r"(a[2]), "r"(a[3]), "r"(b[0]), "r"(b[1]));
}

// split fp32 -> (hi,lo) bf16; pack two adjacent k into one u32 each
__device__ __forceinline__ void split2(float x0, float x1, uint32_t& h, uint32_t& l) {
    __nv_bfloat16 h0 = __float2bfloat16(x0);
    __nv_bfloat16 h1 = __float2bfloat16(x1);
    __nv_bfloat16 l0 = __float2bfloat16(x0 - __bfloat162float(h0));
    __nv_bfloat16 l1 = __float2bfloat16(x1 - __bfloat162float(h1));
    uint16_t hb0 = *reinterpret_cast<uint16_t*>(&h0);
    uint16_t hb1 = *reinterpret_cast<uint16_t*>(&h1);
    uint16_t lb0 = *reinterpret_cast<uint16_t*>(&l0);
    uint16_t lb1 = *reinterpret_cast<uint16_t*>(&l1);
    h = (uint32_t)hb0 | ((uint32_t)hb1 << 16);
    l = (uint32_t)lb0 | ((uint32_t)lb1 << 16);
}

// ---------------- grid barrier ----------------
__device__ __forceinline__ void gbar(int slot, int target) {
    __threadfence();
    __syncthreads();
    if (threadIdx.x == 0) {
        atomicAdd(&g_cnt[slot], 1);
        while (atomicAdd(&g_cnt[slot], 0) < target) __nanosleep(128);
        __threadfence();
    }
    __syncthreads();
}

// ---------------- GEMM stage (mma.sync bf16x3) ----------------
// MODE 0: O = silu(A @ W^T + b)
// MODE 1: O = A + silu(GN(A) @ W^T + b)   (K == hid)
// MODE 2: O = A @ W^T + b
template <int MODE>
__device__ void run_stage(char* sm, uint32_t sb,
                          const float* __restrict__ A, float* __restrict__ O,
                          const float* __restrict__ W, const float* __restrict__ bias,
                          const float* __restrict__ gng, const float* __restrict__ gnb,
                          const float* __restrict__ stat,
                          int K, int hid, int n0, int magic) {
    int tid = threadIdx.x, lane = tid & 31, wid = tid >> 5;
    int mbase = (wid & 3) * 32, nbase = (wid >> 2) * 32;
    int nch = K >> 6;

    float acc[2][4][4];
    #pragma unroll
    for (int i = 0; i < 2; i++)
        #pragma unroll
        for (int j = 0; j < 4; j++)
            #pragma unroll
            for (int e = 0; e < 4; e++) acc[i][j][e] = 0.f;

    int arow = tid >> 1, akc = (tid & 1) * 32;
    int wrow = tid >> 2, wkc = (tid & 3) * 16;
    const float* Aro = A + (size_t)arow * K;
    const float* Wro = W + (size_t)(n0 + wrow) * K;

    float4 ra[8], rw[4];
    #pragma unroll
    for (int j = 0; j < 8; j++) ra[j] = *(const float4*)(Aro + akc + j * 4);
    #pragma unroll
    for (int j = 0; j < 4; j++) rw[j] = *(const float4*)(Wro + wkc + j * 4);

    for (int c = 0; c < nch; c++) {
        char* buf = sm + (c & 1) * BUFB;
        uint32_t bu = sb + (c & 1) * BUFB;

        // convert + store A (with optional GN)
        #pragma unroll
        for (int j = 0; j < 8; j++) {
            float xs[4] = {ra[j].x, ra[j].y, ra[j].z, ra[j].w};
            if (MODE == 1) {
                #pragma unroll
                for (int e = 0; e < 4; e++) {
                    int k = c * 64 + akc + j * 4 + e;
                    int g = (k * magic) >> 16;
                    float gm = stat[arow * 32 + g];
                    float gs = stat[4096 + arow * 32 + g];
                    xs[e] = (xs[e] - gm) * gs * __ldg(gng + k) + __ldg(gnb + k);
                }
            }
            uint32_t h0, l0, h1, l1;
            split2(xs[0], xs[1], h0, l0);
            split2(xs[2], xs[3], h1, l1);
            uint32_t off = (uint32_t)arow * 128 + (akc + j * 4) * 2;
            *(uint32_t*)(buf + swz(off))           = h0;
            *(uint32_t*)(buf + swz(off + 4))       = h1;
            *(uint32_t*)(buf + 16384 + swz(off))   = l0;
            *(uint32_t*)(buf + 16384 + swz(off + 4)) = l1;
        }
        // convert + store W
        #pragma unroll
        for (int j = 0; j < 4; j++) {
            uint32_t h0, l0, h1, l1;
            split2(rw[j].x, rw[j].y, h0, l0);
            split2(rw[j].z, rw[j].w, h1, l1);
            uint32_t off = (uint32_t)wrow * 128 + (wkc + j * 4) * 2;
            *(uint32_t*)(buf + 32768 + swz(off))       = h0;
            *(uint32_t*)(buf + 32768 + swz(off + 4))   = h1;
            *(uint32_t*)(buf + 40960 + swz(off))       = l0;
            *(uint32_t*)(buf + 40960 + swz(off + 4))   = l1;
        }
        __syncthreads();

        // prefetch next chunk while this chunk's MMAs run
        if (c + 1 < nch) {
            #pragma unroll
            for (int j = 0; j < 8; j++) ra[j] = *(const float4*)(Aro + (c + 1) * 64 + akc + j * 4);
            #pragma unroll
            for (int j = 0; j < 4; j++) rw[j] = *(const float4*)(Wro + (c + 1) * 64 + wkc + j * 4);
        }

        #pragma unroll
        for (int ks = 0; ks < 4; ks++) {
            uint32_t bh[4][2], bl[4][2], ah[2][4], al[2][4];
            #pragma unroll
            for (int nt = 0; nt < 4; nt++) {
                uint32_t off = (uint32_t)(nbase + nt * 8 + (lane & 7)) * 128
                             + ks * 32 + ((lane >> 3) & 1) * 16;
                ldsm2(bh[nt], bu + 32768 + swz(off));
                ldsm2(bl[nt], bu + 40960 + swz(off));
            }
            #pragma unroll
            for (int mt = 0; mt < 2; mt++) {
                uint32_t off = (uint32_t)(mbase + mt * 16 + (lane & 15)) * 128
                             + ks * 32 + (lane >> 4) * 16;
                ldsm4(ah[mt], bu + swz(off));
                ldsm4(al[mt], bu + 16384 + swz(off));
            }
            #pragma unroll
            for (int mt = 0; mt < 2; mt++)
                #pragma unroll
                for (int nt = 0; nt < 4; nt++) {
                    mma16816(acc[mt][nt], ah[mt], bh[nt]);
                    mma16816(acc[mt][nt], al[mt], bh[nt]);
                    mma16816(acc[mt][nt], ah[mt], bl[nt]);
                }
        }
        __syncthreads();
    }

    // epilogue
    #pragma unroll
    for (int mt = 0; mt < 2; mt++)
        #pragma unroll
        for (int nt = 0; nt < 4; nt++)
            #pragma unroll
            for (int h = 0; h < 2; h++) {
                int r = mbase + mt * 16 + (lane >> 2) + h * 8;
                int cc = n0 + nbase + nt * 8 + (lane & 3) * 2;
                float v0 = acc[mt][nt][h * 2 + 0] + __ldg(bias + cc);
                float v1 = acc[mt][nt][h * 2 + 1] + __ldg(bias + cc + 1);
                if (MODE <= 1) {
                    v0 = v0 / (1.f + expf(-v0));
                    v1 = v1 / (1.f + expf(-v1));
                }
                if (MODE == 1) {
                    float2 hv = *(const float2*)(A + (size_t)r * hid + cc);
                    v0 += hv.x; v1 += hv.y;
                }
                float2 o2 = {v0, v1};
                *(float2*)(O + (size_t)r * hid + cc) = o2;
            }
}

// ---------------- GN stats pass (16 CTAs per chain, 8 rows each) ----------------
__device__ void stats_pass(const float* __restrict__ hbuf, int cid) {
    int chain = cid >> 4;
    int hid = chain < 4 ? 768 : 1280;
    int gs = hid >> 5;
    float inv = 1.f / (float)gs;
    const float* base = hbuf + ch_off(chain);
    int r = (cid & 15) * 8 + (threadIdx.x >> 5);
    int g = threadIdx.x & 31;
    const float* sp = base + (size_t)r * hid + g * gs;
    float s = 0.f, ss = 0.f;
    for (int j = 0; j < gs; j += 4) {
        float4 v = *(const float4*)(sp + j);
        s  += v.x + v.y + v.z + v.w;
        ss += v.x * v.x + v.y * v.y + v.z * v.z + v.w * v.w;
    }
    float m = s * inv;
    float var = ss * inv - m * m;
    g_stats[chain * 8192 + r * 32 + g] = m;
    g_stats[chain * 8192 + 4096 + r * 32 + g] = rsqrtf(var + 1e-5f);
}

// ---------------- ticketed copy ----------------
__device__ void copy_work(const Params& p, int* s_ticket) {
    const float4* e0 = (const float4*)p.e0;
    const float4* e1 = (const float4*)p.e1;
    const float4* e2 = (const float4*)p.e2;
    float4* o = (float4*)p.out;
    while (true) {
        if (threadIdx.x == 0) *s_ticket = atomicAdd(&g_ticket, 1);
        __syncthreads();
        long base = (long)(*s_ticket) * CHUNK4;
        __syncthreads();
        if (base >= N4T) break;
        long end = base + CHUNK4;
        if (end > N4T) end = N4T;
        #pragma unroll 4
        for (long i = base + threadIdx.x; i < end; i += 256) {
            float4 v;
            if (i < N40)            v = e0[i];
            else if (i < N40 + N41) v = e1[i - N40];
            else                    v = e2[i - N40 - N41];
            o[i] = v;
        }
    }
}

// ---------------- scatter ----------------
__device__ void scatter_all(float* __restrict__ out, int cid) {
    for (int c = cid; c < 80; c += NCOMP) {
        int te = c / 40, rem = c % 40, b = rem / 5, r = rem % 5;
        int np = g_npos[b];
        if (!np) continue;
        int hid = te ? H2C : H1C;
        int t = (r < 4) ? r : 3;
        int chain = te * 4 + t;
        const float* tok = g_bufA + ch_off(chain);
        float* o = te ? out + OUT0_ELEMS + (size_t)b * SSV * H2C
                      : out + (size_t)b * SSV * H1C;
        int h4 = hid >> 2, tot = np * h4;
        for (int e = threadIdx.x; e < tot; e += 256) {
            int i = e / h4, c4 = e % h4;
            int s = (r < 4) ? (SSV - 1 - r * np - i) : (SSV - 5 * np + i);
            float4 v = ((const float4*)(tok + (size_t)(b * 16 + i) * hid))[c4];
            ((float4*)(o + (size_t)s * hid))[c4] = v;
        }
    }
}

// ---------------- kernels ----------------
__global__ void reset_kernel() {
    if (threadIdx.x < 8) g_cnt[threadIdx.x] = 0;
    if (threadIdx.x == 8) g_ticket = 0;
}

__global__ void __launch_bounds__(256, 1) mega_kernel(Params p) {
    extern __shared__ char smraw[];
    __shared__ float red[256];
    __shared__ int s_ticket;
    int cid = blockIdx.x, tid = threadIdx.x;

    if (cid >= NCOMP) {
        copy_work(p, &s_ticket);
        __threadfence();
        __syncthreads();
        if (tid == 0) atomicAdd(&g_cnt[7], 1);
        return;
    }

    // align tile buffers to 1KB for clean swizzle banking
    uint32_t sb0 = s2u(smraw);
    uint32_t sb = (sb0 + 1023) & ~1023u;
    char* sm = smraw + (sb - sb0);

    // npos (CTAs 0..7)
    if (cid < 8) {
        int b = cid, cnt = 0;
        for (int s = 0; s < 16; s++) {
            red[tid] = fabsf(p.extra[((size_t)b * 16 + s) * 704 + 448 + tid]);
            __syncthreads();
            for (int o = 128; o > 0; o >>= 1) {
                if (tid < o) red[tid] += red[tid + o];
                __syncthreads();
            }
            if (tid == 0 && red[0] > 1e-6f) cnt++;
            __syncthreads();
        }
        if (tid == 0) g_npos[b] = cnt;
    }

    // tile decode: 48 CTAs for te1 (4 chains x 12 n-tiles), 80 for te2 (4 x 20)
    int chain, nt, hid;
    if (cid < 48) { chain = cid / 12; nt = cid % 12; hid = 768; }
    else { int c2 = cid - 48; chain = 4 + c2 / 20; nt = c2 % 20; hid = 1280; }
    int te = chain >> 2, t = chain & 3;
    int n0 = nt * 64;
    int magic = (hid == 768) ? 2731 : 1639;
    const float* stat = g_stats + chain * 8192;
    size_t co = ch_off(chain);

    // stage 0: fc1, extra -> bufA
    run_stage<0>(sm, sb, p.extra, g_bufA + co,
                 p.f1w[te] + (size_t)t * hid * 704, p.f1b[te] + t * hid,
                 nullptr, nullptr, nullptr, 704, hid, n0, 0);
    gbar(0, NCOMP);
    stats_pass(g_bufA, cid);
    gbar(1, NCOMP);

    float* bufs[2] = {g_bufA, g_bufB};
    #pragma unroll 1
    for (int l = 0; l < 3; l++) {
        const float* hin = bufs[l & 1] + co;
        float* hout = bufs[(l + 1) & 1] + co;
        size_t wo = (size_t)(t * 3 + l) * hid;
        run_stage<1>(sm, sb, hin, hout,
                     p.bw[te] + wo * hid, p.bb[te] + wo,
                     p.gg[te] + wo, p.gb[te] + wo,
                     stat, hid, hid, n0, magic);
        if (l < 2) {
            gbar(2 + 2 * l, NCOMP);
            stats_pass(bufs[(l + 1) & 1], cid);
            gbar(3 + 2 * l, NCOMP);
        } else {
            gbar(6, NCOMP);
        }
    }

    // out stage: bufB -> bufA (final tokens in bufA)
    run_stage<2>(sm, sb, g_bufB + co, g_bufA + co,
                 p.ow[te] + (size_t)t * hid * hid, p.ob[te] + t * hid,
                 nullptr, nullptr, nullptr, hid, hid, n0, 0);

    // join the big copy, then full-grid barrier
    copy_work(p, &s_ticket);
    gbar(7, NCTA);

    scatter_all(p.out, cid);
}

// ---------------- launch ----------------
extern "C" void kernel_launch(void* const* d_in, const int* in_sizes, int n_in,
                              void* d_out, int out_size) {
    Params p;
    p.e0    = (const float*)d_in[0];
    p.e1    = (const float*)d_in[1];
    p.e2    = (const float*)d_in[2];
    p.extra = (const float*)d_in[3];
    p.f1w[0] = (const float*)d_in[4];  p.f1b[0] = (const float*)d_in[5];
    p.gg[0]  = (const float*)d_in[6];  p.gb[0]  = (const float*)d_in[7];
    p.bw[0]  = (const float*)d_in[8];  p.bb[0]  = (const float*)d_in[9];
    p.ow[0]  = (const float*)d_in[10]; p.ob[0]  = (const float*)d_in[11];
    p.f1w[1] = (const float*)d_in[12]; p.f1b[1] = (const float*)d_in[13];
    p.gg[1]  = (const float*)d_in[14]; p.gb[1]  = (const float*)d_in[15];
    p.bw[1]  = (const float*)d_in[16]; p.bb[1]  = (const float*)d_in[17];
    p.ow[1]  = (const float*)d_in[18]; p.ob[1]  = (const float*)d_in[19];
    p.out = (float*)d_out;

    cudaFuncSetAttribute(mega_kernel, cudaFuncAttributeMaxDynamicSharedMemorySize, SMEM_BYTES);

    reset_kernel<<<1, 32>>>();
    mega_kernel<<<NCTA, 256, SMEM_BYTES>>>(p);
}

// round 4
// speedup vs baseline: 2.3895x; 1.7106x over previous
#include <cuda_runtime.h>
#include <cuda_bf16.h>
#include <math.h>
#include <stdint.h>

// ---------------- problem constants ----------------
#define SSV 4096
#define H1C 768
#define H2C 1280

static constexpr long OUT0_ELEMS = 8L * 4096L * 768L;
static constexpr long OUT1_ELEMS = 8L * 4096L * 1280L;
static constexpr long OUT2_ELEMS = 8L * 2816L;

static constexpr long N40 = OUT0_ELEMS / 4;
static constexpr long N41 = OUT1_ELEMS / 4;
static constexpr long N42 = OUT2_ELEMS / 4;
static constexpr long N4T = N40 + N41 + N42;

static constexpr int NCOMP = 64;     // compute CTAs: one 128x128 tile each
static constexpr int NCTA  = 148;
static constexpr int CHUNK4 = 16384; // float4 per copy ticket (256KB)

// smem: two 32KB buffers (chunk K=32):
//   Ah[128x32 bf16]=8K @0, Al=8K @8192, Wh[128x32]=8K @16384, Wl=8K @24576
static constexpr int BUFB = 32768;
static constexpr int SMEM_BYTES = 1024 + 2 * BUFB;

// ---------------- device globals ----------------
__device__ float g_bufA[1048576];
__device__ float g_bufB[1048576];
__device__ float g_sum[3 * 8 * 4096];   // [stage][chain][row(128)][grp(32)]
__device__ float g_ss[3 * 8 * 4096];
__device__ int   g_npos[8];
__device__ int   g_cbar[32];            // per-chain barriers [chain][stage]
__device__ int   g_gbar;
__device__ int   g_ticket;

__device__ __forceinline__ size_t ch_off(int c) {
    return (c < 4) ? (size_t)c * 128 * 768
                   : (size_t)4 * 128 * 768 + (size_t)(c - 4) * 128 * 1280;
}

struct Params {
    const float* extra;
    const float* f1w[2]; const float* f1b[2];
    const float* gg[2];  const float* gb[2];
    const float* bw[2];  const float* bb[2];
    const float* ow[2];  const float* ob[2];
    const float* e0; const float* e1; const float* e2;
    float* out;
};

// ---------------- helpers ----------------
__device__ __forceinline__ uint32_t s2u(const void* p) {
    uint32_t a;
    asm("{ .reg .u64 t; cvta.to.shared.u64 t, %1; cvt.u32.u64 %0, t; }" : "=r"(a) : "l"(p));
    return a;
}
__device__ __forceinline__ uint32_t swz64(uint32_t o) { return o ^ ((o >> 3) & 0x30); }

__device__ __forceinline__ void ldsm4(uint32_t* r, uint32_t a) {
    asm volatile("ldmatrix.sync.aligned.m8n8.x4.shared.b16 {%0,%1,%2,%3}, [%4];"
                 : "=r"(r[0]), "=r"(r[1]), "=r"(r[2]), "=r"(r[3]) : "r"(a));
}
__device__ __forceinline__ void ldsm2(uint32_t* r, uint32_t a) {
    asm volatile("ldmatrix.sync.aligned.m8n8.x2.shared.b16 {%0,%1}, [%2];"
                 : "=r"(r[0]), "=r"(r[1]) : "r"(a));
}
__device__ __forceinline__ void mma16816(float* d, const uint32_t* a, const uint32_t* b) {
    asm volatile(
        "mma.sync.aligned.m16n8k16.row.col.f32.bf16.bf16.f32 "
        "{%0,%1,%2,%3}, {%4,%5,%6,%7}, {%8,%9}, {%0,%1,%2,%3};"
        : "+f"(d[0]), "+f"(d[1]), "+f"(d[2]), "+f"(d[3])
        : "r"(a[0]), "r"(a[1]), "r"(a[2]), "r"(a[3]), "r"(b[0]), "r"(b[1]));
}

__device__ __forceinline__ void split2(float x0, float x1, uint32_t& h, uint32_t& l) {
    __nv_bfloat16 h0 = __float2bfloat16(x0);
    __nv_bfloat16 h1 = __float2bfloat16(x1);
    __nv_bfloat16 l0 = __float2bfloat16(x0 - __bfloat162float(h0));
    __nv_bfloat16 l1 = __float2bfloat16(x1 - __bfloat162float(h1));
    uint16_t hb0 = *reinterpret_cast<uint16_t*>(&h0);
    uint16_t hb1 = *reinterpret_cast<uint16_t*>(&h1);
    uint16_t lb0 = *reinterpret_cast<uint16_t*>(&l0);
    uint16_t lb1 = *reinterpret_cast<uint16_t*>(&l1);
    h = (uint32_t)hb0 | ((uint32_t)hb1 << 16);
    l = (uint32_t)lb0 | ((uint32_t)lb1 << 16);
}

// ---------------- barriers (arrive + spin) ----------------
__device__ __forceinline__ void barrier_on(int* cnt, int target) {
    __threadfence();
    __syncthreads();
    if (threadIdx.x == 0) {
        atomicAdd(cnt, 1);
        while (*(volatile int*)cnt < target) __nanosleep(64);
        __threadfence();
    }
    __syncthreads();
}

// ---------------- GEMM stage ----------------
// MODE 0: O = silu(A @ W^T + b)
// MODE 1: O = A + silu(GN(A) @ W^T + b)   (K == hid)
// MODE 2: O = A @ W^T + b
template <int MODE, bool STATS>
__device__ void run_stage(char* sm, uint32_t sb,
                          const float* __restrict__ A, float* __restrict__ O,
                          const float* __restrict__ W, const float* __restrict__ bias,
                          const float* __restrict__ gng, const float* __restrict__ gnb,
                          const float* __restrict__ rs_s, const float* __restrict__ rs_q,
                          float* __restrict__ ws_s, float* __restrict__ ws_q,
                          int K, int hid, int n0, int magic, float inv_gs) {
    int tid = threadIdx.x, lane = tid & 31, wid = tid >> 5;
    int mbase = (wid & 3) * 32, nbase = (wid >> 2) * 64;
    int nch = K >> 5;
    int row0 = tid >> 3, c4 = tid & 7;

    const float* Arow = A + (size_t)row0 * K + c4 * 4;
    const float* Wrow = W + (size_t)(n0 + row0) * K + c4 * 4;

    float acc[2][8][4];
    #pragma unroll
    for (int i = 0; i < 2; i++)
        #pragma unroll
        for (int j = 0; j < 8; j++)
            #pragma unroll
            for (int e = 0; e < 4; e++) acc[i][j][e] = 0.f;

    float4 ra[4], rw[4];
    #pragma unroll
    for (int j = 0; j < 4; j++) ra[j] = *(const float4*)(Arow + (size_t)(32 * j) * K);
    #pragma unroll
    for (int j = 0; j < 4; j++) rw[j] = *(const float4*)(Wrow + (size_t)(32 * j) * K);

    for (int c = 0; c < nch; c++) {
        char* buf = sm + (c & 1) * BUFB;
        uint32_t bu = sb + (c & 1) * BUFB;

        // ---- convert + store A ----
        #pragma unroll
        for (int j = 0; j < 4; j++) {
            int row = row0 + 32 * j;
            float xs[4] = {ra[j].x, ra[j].y, ra[j].z, ra[j].w};
            if (MODE == 1) {
                int k = c * 32 + c4 * 4;
                int g = (k * magic) >> 16;
                float s = __ldg(rs_s + row * 32 + g);
                float q = __ldg(rs_q + row * 32 + g);
                float mean = s * inv_gs;
                float var = q * inv_gs - mean * mean;
                float rstd = rsqrtf(fmaxf(var, 0.f) + 1e-5f);
                float4 gw = *(const float4*)(gng + k);
                float4 gb = *(const float4*)(gnb + k);
                xs[0] = (xs[0] - mean) * rstd * gw.x + gb.x;
                xs[1] = (xs[1] - mean) * rstd * gw.y + gb.y;
                xs[2] = (xs[2] - mean) * rstd * gw.z + gb.z;
                xs[3] = (xs[3] - mean) * rstd * gw.w + gb.w;
            }
            uint32_t h0, l0, h1, l1;
            split2(xs[0], xs[1], h0, l0);
            split2(xs[2], xs[3], h1, l1);
            uint32_t off = swz64((uint32_t)row * 64 + c4 * 8);
            *(uint2*)(buf + off)        = make_uint2(h0, h1);
            *(uint2*)(buf + 8192 + off) = make_uint2(l0, l1);
        }
        // ---- convert + store W ----
        #pragma unroll
        for (int j = 0; j < 4; j++) {
            uint32_t h0, l0, h1, l1;
            split2(rw[j].x, rw[j].y, h0, l0);
            split2(rw[j].z, rw[j].w, h1, l1);
            uint32_t off = swz64((uint32_t)(row0 + 32 * j) * 64 + c4 * 8);
            *(uint2*)(buf + 16384 + off) = make_uint2(h0, h1);
            *(uint2*)(buf + 24576 + off) = make_uint2(l0, l1);
        }
        __syncthreads();

        // ---- prefetch next chunk ----
        if (c + 1 < nch) {
            int kb = (c + 1) * 32;
            #pragma unroll
            for (int j = 0; j < 4; j++) ra[j] = *(const float4*)(Arow + (size_t)(32 * j) * K + kb);
            #pragma unroll
            for (int j = 0; j < 4; j++) rw[j] = *(const float4*)(Wrow + (size_t)(32 * j) * K + kb);
        }

        // ---- MMA ----
        #pragma unroll
        for (int ks = 0; ks < 2; ks++) {
            uint32_t ah[2][4], al[2][4], bh[8][2], bl[8][2];
            #pragma unroll
            for (int mt = 0; mt < 2; mt++) {
                uint32_t off = (uint32_t)(mbase + mt * 16 + (lane & 15)) * 64
                             + ks * 32 + (lane >> 4) * 16;
                ldsm4(ah[mt], bu + swz64(off));
                ldsm4(al[mt], bu + 8192 + swz64(off));
            }
            #pragma unroll
            for (int nt = 0; nt < 8; nt++) {
                uint32_t off = (uint32_t)(nbase + nt * 8 + (lane & 7)) * 64
                             + ks * 32 + ((lane >> 3) & 1) * 16;
                ldsm2(bh[nt], bu + 16384 + swz64(off));
                ldsm2(bl[nt], bu + 24576 + swz64(off));
            }
            #pragma unroll
            for (int mt = 0; mt < 2; mt++)
                #pragma unroll
                for (int nt = 0; nt < 8; nt++) {
                    mma16816(acc[mt][nt], ah[mt], bh[nt]);
                    mma16816(acc[mt][nt], al[mt], bh[nt]);
                    mma16816(acc[mt][nt], ah[mt], bl[nt]);
                }
        }
    }
    __syncthreads();

    // ---- epilogue ----
    #pragma unroll
    for (int mt = 0; mt < 2; mt++)
        #pragma unroll
        for (int nt = 0; nt < 8; nt++) {
            int cc = n0 + nbase + nt * 8 + (lane & 3) * 2;
            int gblk = ((n0 + nbase + nt * 8) * magic) >> 16;
            #pragma unroll
            for (int h = 0; h < 2; h++) {
                int r = mbase + mt * 16 + (lane >> 2) + h * 8;
                float v0 = acc[mt][nt][h * 2 + 0] + __ldg(bias + cc);
                float v1 = acc[mt][nt][h * 2 + 1] + __ldg(bias + cc + 1);
                if (MODE <= 1) {
                    v0 = v0 / (1.f + __expf(-v0));
                    v1 = v1 / (1.f + __expf(-v1));
                }
                if (MODE == 1) {
                    float2 rv = *(const float2*)(A + (size_t)r * hid + cc);
                    v0 += rv.x; v1 += rv.y;
                }
                float2 o2 = {v0, v1};
                *(float2*)(O + (size_t)r * hid + cc) = o2;
                if (STATS) {
                    float p = v0 + v1;
                    float q = v0 * v0 + v1 * v1;
                    p += __shfl_xor_sync(0xffffffff, p, 1);
                    q += __shfl_xor_sync(0xffffffff, q, 1);
                    p += __shfl_xor_sync(0xffffffff, p, 2);
                    q += __shfl_xor_sync(0xffffffff, q, 2);
                    if ((lane & 3) == 0) {
                        atomicAdd(ws_s + r * 32 + gblk, p);
                        atomicAdd(ws_q + r * 32 + gblk, q);
                    }
                }
            }
        }
}

// ---------------- ticketed copy (uniform source per ticket) ----------------
__device__ void copy_work(const Params& p, int* s_ticket) {
    float4* o = (float4*)p.out;
    while (true) {
        if (threadIdx.x == 0) *s_ticket = atomicAdd(&g_ticket, 1);
        __syncthreads();
        long base = (long)(*s_ticket) * CHUNK4;
        __syncthreads();
        if (base >= N4T) break;
        const float4* src; long off;
        if (base < N40)            { src = (const float4*)p.e0; off = base; }
        else if (base < N40 + N41) { src = (const float4*)p.e1; off = base - N40; }
        else                       { src = (const float4*)p.e2; off = base - N40 - N41; }
        long end = base + CHUNK4;
        if (end > N4T) end = N4T;
        long n = end - base;
        #pragma unroll 4
        for (long i = threadIdx.x; i < n; i += 256)
            o[base + i] = src[off + i];
    }
}

// ---------------- scatter ----------------
__device__ void scatter_all(float* __restrict__ out, int cid) {
    for (int c = cid; c < 80; c += NCTA) {
        int te = c / 40, rem = c % 40, b = rem / 5, r = rem % 5;
        int np = g_npos[b];
        if (!np) continue;
        int hid = te ? H2C : H1C;
        int t = (r < 4) ? r : 3;
        int chain = te * 4 + t;
        const float* tok = g_bufA + ch_off(chain);
        float* o = te ? out + OUT0_ELEMS + (size_t)b * SSV * H2C
                      : out + (size_t)b * SSV * H1C;
        int h4 = hid >> 2, tot = np * h4;
        for (int e = threadIdx.x; e < tot; e += 256) {
            int i = e / h4, c4 = e % h4;
            int s = (r < 4) ? (SSV - 1 - r * np - i) : (SSV - 5 * np + i);
            float4 v = ((const float4*)(tok + (size_t)(b * 16 + i) * hid))[c4];
            ((float4*)(o + (size_t)s * hid))[c4] = v;
        }
    }
}

// ---------------- kernels ----------------
__global__ void reset_kernel() {
    int idx = blockIdx.x * 256 + threadIdx.x;
    if (idx < 3 * 8 * 4096) { g_sum[idx] = 0.f; g_ss[idx] = 0.f; }
    if (idx < 32) g_cbar[idx] = 0;
    if (idx == 32) { g_gbar = 0; g_ticket = 0; }
}

__global__ void __launch_bounds__(256, 1) mega_kernel(Params p) {
    extern __shared__ char smraw[];
    __shared__ float red[256];
    __shared__ int s_ticket;
    int cid = blockIdx.x, tid = threadIdx.x;

    if (cid >= NCOMP) {
        copy_work(p, &s_ticket);
        barrier_on(&g_gbar, NCTA);
        scatter_all(p.out, cid);
        return;
    }

    uint32_t sb0 = s2u(smraw);
    uint32_t sb = (sb0 + 1023) & ~1023u;
    char* sm = smraw + (sb - sb0);

    // npos (CTAs 0..7), needed only by the final scatter
    if (cid < 8) {
        int b = cid, cnt = 0;
        for (int s = 0; s < 16; s++) {
            red[tid] = fabsf(p.extra[((size_t)b * 16 + s) * 704 + 448 + tid]);
            __syncthreads();
            for (int o = 128; o > 0; o >>= 1) {
                if (tid < o) red[tid] += red[tid + o];
                __syncthreads();
            }
            if (tid == 0 && red[0] > 1e-6f) cnt++;
            __syncthreads();
        }
        if (tid == 0) g_npos[b] = cnt;
    }

    // tile decode: 24 CTAs te1 (4 chains x 6 n-tiles), 40 CTAs te2 (4 x 10)
    int chain, nt, hid, nc_chain;
    if (cid < 24) { chain = cid / 6; nt = cid % 6; hid = 768; nc_chain = 6; }
    else { int c2 = cid - 24; chain = 4 + c2 / 10; nt = c2 % 10; hid = 1280; nc_chain = 10; }
    int te = chain >> 2, t = chain & 3;
    int n0 = nt * 128;
    int magic = (hid == 768) ? 2731 : 1639;
    float inv_gs = 1.f / (float)(hid >> 5);
    size_t co = ch_off(chain);

    float* st_s0 = g_sum + (0 * 8 + chain) * 4096; float* st_q0 = g_ss + (0 * 8 + chain) * 4096;
    float* st_s1 = g_sum + (1 * 8 + chain) * 4096; float* st_q1 = g_ss + (1 * 8 + chain) * 4096;
    float* st_s2 = g_sum + (2 * 8 + chain) * 4096; float* st_q2 = g_ss + (2 * 8 + chain) * 4096;
    int* cb = g_cbar + chain * 4;

    // s0: fc1 (K=704), extra -> bufA, stats -> slot0
    run_stage<0, true>(sm, sb, p.extra, g_bufA + co,
                       p.f1w[te] + (size_t)t * hid * 704, p.f1b[te] + t * hid,
                       nullptr, nullptr, nullptr, nullptr, st_s0, st_q0,
                       704, hid, n0, magic, inv_gs);
    barrier_on(cb + 0, nc_chain);

    // s1: block0, bufA -> bufB, read stats0, write stats1
    {
        size_t wo = (size_t)(t * 3 + 0) * hid;
        run_stage<1, true>(sm, sb, g_bufA + co, g_bufB + co,
                           p.bw[te] + wo * hid, p.bb[te] + wo,
                           p.gg[te] + wo, p.gb[te] + wo, st_s0, st_q0, st_s1, st_q1,
                           hid, hid, n0, magic, inv_gs);
    }
    barrier_on(cb + 1, nc_chain);

    // s2: block1, bufB -> bufA, read stats1, write stats2
    {
        size_t wo = (size_t)(t * 3 + 1) * hid;
        run_stage<1, true>(sm, sb, g_bufB + co, g_bufA + co,
                           p.bw[te] + wo * hid, p.bb[te] + wo,
                           p.gg[te] + wo, p.gb[te] + wo, st_s1, st_q1, st_s2, st_q2,
                           hid, hid, n0, magic, inv_gs);
    }
    barrier_on(cb + 2, nc_chain);

    // s3: block2, bufA -> bufB, read stats2
    {
        size_t wo = (size_t)(t * 3 + 2) * hid;
        run_stage<1, false>(sm, sb, g_bufA + co, g_bufB + co,
                            p.bw[te] + wo * hid, p.bb[te] + wo,
                            p.gg[te] + wo, p.gb[te] + wo, st_s2, st_q2, nullptr, nullptr,
                            hid, hid, n0, magic, inv_gs);
    }
    barrier_on(cb + 3, nc_chain);

    // s4: out projection, bufB -> bufA (final tokens in bufA)
    run_stage<2, false>(sm, sb, g_bufB + co, g_bufA + co,
                        p.ow[te] + (size_t)t * hid * hid, p.ob[te] + t * hid,
                        nullptr, nullptr, nullptr, nullptr, nullptr, nullptr,
                        hid, hid, n0, magic, inv_gs);

    // join the big copy, then one global barrier, then scatter
    copy_work(p, &s_ticket);
    barrier_on(&g_gbar, NCTA);
    scatter_all(p.out, cid);
}

// ---------------- launch ----------------
extern "C" void kernel_launch(void* const* d_in, const int* in_sizes, int n_in,
                              void* d_out, int out_size) {
    Params p;
    p.e0    = (const float*)d_in[0];
    p.e1    = (const float*)d_in[1];
    p.e2    = (const float*)d_in[2];
    p.extra = (const float*)d_in[3];
    p.f1w[0] = (const float*)d_in[4];  p.f1b[0] = (const float*)d_in[5];
    p.gg[0]  = (const float*)d_in[6];  p.gb[0]  = (const float*)d_in[7];
    p.bw[0]  = (const float*)d_in[8];  p.bb[0]  = (const float*)d_in[9];
    p.ow[0]  = (const float*)d_in[10]; p.ob[0]  = (const float*)d_in[11];
    p.f1w[1] = (const float*)d_in[12]; p.f1b[1] = (const float*)d_in[13];
    p.gg[1]  = (const float*)d_in[14]; p.gb[1]  = (const float*)d_in[15];
    p.bw[1]  = (const float*)d_in[16]; p.bb[1]  = (const float*)d_in[17];
    p.ow[1]  = (const float*)d_in[18]; p.ob[1]  = (const float*)d_in[19];
    p.out = (float*)d_out;

    cudaFuncSetAttribute(mega_kernel, cudaFuncAttributeMaxDynamicSharedMemorySize, SMEM_BYTES);

    reset_kernel<<<(3 * 8 * 4096 + 255) / 256, 256>>>();
    mega_kernel<<<NCTA, 256, SMEM_BYTES>>>(p);
}

// round 5
// speedup vs baseline: 2.6913x; 1.1263x over previous
#include <cuda_runtime.h>
#include <cuda_bf16.h>
#include <math.h>
#include <stdint.h>

// ---------------- problem constants ----------------
#define SSV 4096
#define H1C 768
#define H2C 1280

static constexpr long OUT0_ELEMS = 8L * 4096L * 768L;
static constexpr long OUT1_ELEMS = 8L * 4096L * 1280L;
static constexpr long OUT2_ELEMS = 8L * 2816L;

static constexpr long N40 = OUT0_ELEMS / 4;
static constexpr long N41 = OUT1_ELEMS / 4;
static constexpr long N42 = OUT2_ELEMS / 4;
static constexpr long N4T = N40 + N41 + N42;

static constexpr int NCOMP = 64;     // compute CTAs: one 128x128 tile each
static constexpr int NCTA  = 148;
static constexpr int NTHR  = 512;
static constexpr int CHUNK4 = 16384; // float4 per copy ticket (256KB)

// smem: two 32KB buffers (chunk K=32):
//   Ah[128x32 bf16]=8K @0, Al=8K @8192, Wh[128x32]=8K @16384, Wl=8K @24576
static constexpr int BUFB = 32768;
static constexpr int SMEM_BYTES = 1024 + 2 * BUFB;

// ---------------- device globals ----------------
__device__ float g_bufA[1048576];
__device__ float g_bufB[1048576];
__device__ float g_sum[3 * 8 * 4096];   // [stage][chain][row(128)][grp(32)]
__device__ float g_ss[3 * 8 * 4096];
__device__ int   g_npos[8];
__device__ int   g_cbar[32];            // per-chain barriers [chain][stage]
__device__ int   g_gbar;
__device__ int   g_ticket;

__device__ __forceinline__ size_t ch_off(int c) {
    return (c < 4) ? (size_t)c * 128 * 768
                   : (size_t)4 * 128 * 768 + (size_t)(c - 4) * 128 * 1280;
}

struct Params {
    const float* extra;
    const float* f1w[2]; const float* f1b[2];
    const float* gg[2];  const float* gb[2];
    const float* bw[2];  const float* bb[2];
    const float* ow[2];  const float* ob[2];
    const float* e0; const float* e1; const float* e2;
    float* out;
};

// ---------------- helpers ----------------
__device__ __forceinline__ uint32_t s2u(const void* p) {
    uint32_t a;
    asm("{ .reg .u64 t; cvta.to.shared.u64 t, %1; cvt.u32.u64 %0, t; }" : "=r"(a) : "l"(p));
    return a;
}
__device__ __forceinline__ uint32_t swz64(uint32_t o) { return o ^ ((o >> 3) & 0x30); }

__device__ __forceinline__ void ldsm4(uint32_t* r, uint32_t a) {
    asm volatile("ldmatrix.sync.aligned.m8n8.x4.shared.b16 {%0,%1,%2,%3}, [%4];"
                 : "=r"(r[0]), "=r"(r[1]), "=r"(r[2]), "=r"(r[3]) : "r"(a));
}
__device__ __forceinline__ void ldsm2(uint32_t* r, uint32_t a) {
    asm volatile("ldmatrix.sync.aligned.m8n8.x2.shared.b16 {%0,%1}, [%2];"
                 : "=r"(r[0]), "=r"(r[1]) : "r"(a));
}
__device__ __forceinline__ void mma16816(float* d, const uint32_t* a, const uint32_t* b) {
    asm volatile(
        "mma.sync.aligned.m16n8k16.row.col.f32.bf16.bf16.f32 "
        "{%0,%1,%2,%3}, {%4,%5,%6,%7}, {%8,%9}, {%0,%1,%2,%3};"
        : "+f"(d[0]), "+f"(d[1]), "+f"(d[2]), "+f"(d[3])
        : "r"(a[0]), "r"(a[1]), "r"(a[2]), "r"(a[3]), "r"(b[0]), "r"(b[1]));
}

__device__ __forceinline__ void split2(float x0, float x1, uint32_t& h, uint32_t& l) {
    __nv_bfloat16 h0 = __float2bfloat16(x0);
    __nv_bfloat16 h1 = __float2bfloat16(x1);
    __nv_bfloat16 l0 = __float2bfloat16(x0 - __bfloat162float(h0));
    __nv_bfloat16 l1 = __float2bfloat16(x1 - __bfloat162float(h1));
    uint16_t hb0 = *reinterpret_cast<uint16_t*>(&h0);
    uint16_t hb1 = *reinterpret_cast<uint16_t*>(&h1);
    uint16_t lb0 = *reinterpret_cast<uint16_t*>(&l0);
    uint16_t lb1 = *reinterpret_cast<uint16_t*>(&l1);
    h = (uint32_t)hb0 | ((uint32_t)hb1 << 16);
    l = (uint32_t)lb0 | ((uint32_t)lb1 << 16);
}

// ---------------- barrier (arrive + spin) ----------------
__device__ __forceinline__ void barrier_on(int* cnt, int target) {
    __threadfence();
    __syncthreads();
    if (threadIdx.x == 0) {
        atomicAdd(cnt, 1);
        while (*(volatile int*)cnt < target) __nanosleep(64);
        __threadfence();
    }
    __syncthreads();
}

// ---------------- GEMM stage ----------------
// MODE 0: O = silu(A @ W^T + b)
// MODE 1: O = A + silu(GN(A) @ W^T + b)   (K == hid)
// MODE 2: O = A @ W^T + b
template <int MODE, bool STATS>
__device__ void run_stage(char* sm, uint32_t sb,
                          const float* __restrict__ A, float* __restrict__ O,
                          const float* __restrict__ W, const float* __restrict__ bias,
                          const float* __restrict__ gng, const float* __restrict__ gnb,
                          const float* __restrict__ rs_s, const float* __restrict__ rs_q,
                          float* __restrict__ ws_s, float* __restrict__ ws_q,
                          int K, int hid, int n0, int magic, float inv_gs) {
    int tid = threadIdx.x, lane = tid & 31, wid = tid >> 5;
    int mbase = (wid & 3) * 32, nbase = (wid >> 2) * 32;
    int nch = K >> 5;
    int row0 = tid >> 2, cb8 = (tid & 3) * 8;   // 4 threads/row, 8 cols each

    const float* Arow = A + (size_t)row0 * K + cb8;
    const float* Wrow = W + (size_t)(n0 + row0) * K + cb8;

    float acc[2][4][4];
    #pragma unroll
    for (int i = 0; i < 2; i++)
        #pragma unroll
        for (int j = 0; j < 4; j++)
            #pragma unroll
            for (int e = 0; e < 4; e++) acc[i][j][e] = 0.f;

    float4 ra[2], rw[2];
    ra[0] = *(const float4*)(Arow);
    ra[1] = *(const float4*)(Arow + 4);
    rw[0] = *(const float4*)(Wrow);
    rw[1] = *(const float4*)(Wrow + 4);

    for (int c = 0; c < nch; c++) {
        char* buf = sm + (c & 1) * BUFB;
        uint32_t bu = sb + (c & 1) * BUFB;

        // ---- convert + store A (8 elems -> one uint4 per buffer) ----
        {
            float xs[8] = {ra[0].x, ra[0].y, ra[0].z, ra[0].w,
                           ra[1].x, ra[1].y, ra[1].z, ra[1].w};
            if (MODE == 1) {
                int k = c * 32 + cb8;
                int g = (k * magic) >> 16;     // 8-col span stays in one group (gs%8==0)
                float s = __ldg(rs_s + row0 * 32 + g);
                float q = __ldg(rs_q + row0 * 32 + g);
                float mean = s * inv_gs;
                float var = q * inv_gs - mean * mean;
                float rstd = rsqrtf(fmaxf(var, 0.f) + 1e-5f);
                #pragma unroll
                for (int e = 0; e < 8; e++)
                    xs[e] = (xs[e] - mean) * rstd * __ldg(gng + k + e) + __ldg(gnb + k + e);
            }
            uint4 hv, lv;
            split2(xs[0], xs[1], hv.x, lv.x);
            split2(xs[2], xs[3], hv.y, lv.y);
            split2(xs[4], xs[5], hv.z, lv.z);
            split2(xs[6], xs[7], hv.w, lv.w);
            uint32_t off = swz64((uint32_t)row0 * 64 + (tid & 3) * 16);
            *(uint4*)(buf + off)        = hv;
            *(uint4*)(buf + 8192 + off) = lv;
        }
        // ---- convert + store W ----
        {
            uint4 hv, lv;
            split2(rw[0].x, rw[0].y, hv.x, lv.x);
            split2(rw[0].z, rw[0].w, hv.y, lv.y);
            split2(rw[1].x, rw[1].y, hv.z, lv.z);
            split2(rw[1].z, rw[1].w, hv.w, lv.w);
            uint32_t off = swz64((uint32_t)row0 * 64 + (tid & 3) * 16);
            *(uint4*)(buf + 16384 + off) = hv;
            *(uint4*)(buf + 24576 + off) = lv;
        }
        __syncthreads();

        // ---- prefetch next chunk ----
        if (c + 1 < nch) {
            int kb = (c + 1) * 32;
            ra[0] = *(const float4*)(Arow + kb);
            ra[1] = *(const float4*)(Arow + kb + 4);
            rw[0] = *(const float4*)(Wrow + kb);
            rw[1] = *(const float4*)(Wrow + kb + 4);
        }

        // ---- MMA ----
        #pragma unroll
        for (int ks = 0; ks < 2; ks++) {
            uint32_t ah[2][4], al[2][4], bh[4][2], bl[4][2];
            #pragma unroll
            for (int mt = 0; mt < 2; mt++) {
                uint32_t off = (uint32_t)(mbase + mt * 16 + (lane & 15)) * 64
                             + ks * 32 + (lane >> 4) * 16;
                ldsm4(ah[mt], bu + swz64(off));
                ldsm4(al[mt], bu + 8192 + swz64(off));
            }
            #pragma unroll
            for (int nt = 0; nt < 4; nt++) {
                uint32_t off = (uint32_t)(nbase + nt * 8 + (lane & 7)) * 64
                             + ks * 32 + ((lane >> 3) & 1) * 16;
                ldsm2(bh[nt], bu + 16384 + swz64(off));
                ldsm2(bl[nt], bu + 24576 + swz64(off));
            }
            #pragma unroll
            for (int mt = 0; mt < 2; mt++)
                #pragma unroll
                for (int nt = 0; nt < 4; nt++) {
                    mma16816(acc[mt][nt], ah[mt], bh[nt]);
                    mma16816(acc[mt][nt], al[mt], bh[nt]);
                    mma16816(acc[mt][nt], ah[mt], bl[nt]);
                }
        }
    }
    __syncthreads();

    // ---- epilogue ----
    #pragma unroll
    for (int mt = 0; mt < 2; mt++)
        #pragma unroll
        for (int nt = 0; nt < 4; nt++) {
            int cc = n0 + nbase + nt * 8 + (lane & 3) * 2;
            int gblk = ((n0 + nbase + nt * 8) * magic) >> 16;
            #pragma unroll
            for (int h = 0; h < 2; h++) {
                int r = mbase + mt * 16 + (lane >> 2) + h * 8;
                float v0 = acc[mt][nt][h * 2 + 0] + __ldg(bias + cc);
                float v1 = acc[mt][nt][h * 2 + 1] + __ldg(bias + cc + 1);
                if (MODE <= 1) {
                    v0 = v0 / (1.f + __expf(-v0));
                    v1 = v1 / (1.f + __expf(-v1));
                }
                if (MODE == 1) {
                    float2 rv = *(const float2*)(A + (size_t)r * hid + cc);
                    v0 += rv.x; v1 += rv.y;
                }
                float2 o2 = {v0, v1};
                *(float2*)(O + (size_t)r * hid + cc) = o2;
                if (STATS) {
                    float p = v0 + v1;
                    float q = v0 * v0 + v1 * v1;
                    p += __shfl_xor_sync(0xffffffff, p, 1);
                    q += __shfl_xor_sync(0xffffffff, q, 1);
                    p += __shfl_xor_sync(0xffffffff, p, 2);
                    q += __shfl_xor_sync(0xffffffff, q, 2);
                    if ((lane & 3) == 0) {
                        atomicAdd(ws_s + r * 32 + gblk, p);
                        atomicAdd(ws_q + r * 32 + gblk, q);
                    }
                }
            }
        }
}

// ---------------- ticketed copy ----------------
__device__ void copy_work(const Params& p, int* s_ticket) {
    float4* o = (float4*)p.out;
    while (true) {
        if (threadIdx.x == 0) *s_ticket = atomicAdd(&g_ticket, 1);
        __syncthreads();
        long base = (long)(*s_ticket) * CHUNK4;
        __syncthreads();
        if (base >= N4T) break;
        const float4* src; long off;
        if (base < N40)            { src = (const float4*)p.e0; off = base; }
        else if (base < N40 + N41) { src = (const float4*)p.e1; off = base - N40; }
        else                       { src = (const float4*)p.e2; off = base - N40 - N41; }
        long end = base + CHUNK4;
        if (end > N4T) end = N4T;
        long n = end - base;
        #pragma unroll 4
        for (long i = threadIdx.x; i < n; i += NTHR)
            o[base + i] = src[off + i];
    }
}

// ---------------- scatter ----------------
__device__ void scatter_all(float* __restrict__ out, int cid) {
    for (int c = cid; c < 80; c += NCTA) {
        int te = c / 40, rem = c % 40, b = rem / 5, r = rem % 5;
        int np = g_npos[b];
        if (!np) continue;
        int hid = te ? H2C : H1C;
        int t = (r < 4) ? r : 3;
        int chain = te * 4 + t;
        const float* tok = g_bufA + ch_off(chain);
        float* o = te ? out + OUT0_ELEMS + (size_t)b * SSV * H2C
                      : out + (size_t)b * SSV * H1C;
        int h4 = hid >> 2, tot = np * h4;
        for (int e = threadIdx.x; e < tot; e += NTHR) {
            int i = e / h4, c4 = e % h4;
            int s = (r < 4) ? (SSV - 1 - r * np - i) : (SSV - 5 * np + i);
            float4 v = ((const float4*)(tok + (size_t)(b * 16 + i) * hid))[c4];
            ((float4*)(o + (size_t)s * hid))[c4] = v;
        }
    }
}

// ---------------- kernels ----------------
__global__ void reset_kernel() {
    int idx = blockIdx.x * 256 + threadIdx.x;
    if (idx < 3 * 8 * 4096) { g_sum[idx] = 0.f; g_ss[idx] = 0.f; }
    if (idx < 32) g_cbar[idx] = 0;
    if (idx == 32) { g_gbar = 0; g_ticket = 0; }
}

__global__ void __launch_bounds__(NTHR, 1) mega_kernel(Params p) {
    extern __shared__ char smraw[];
    __shared__ int s_ticket;
    int cid = blockIdx.x, tid = threadIdx.x;

    if (cid >= NCOMP) {
        copy_work(p, &s_ticket);
        barrier_on(&g_gbar, NCTA);
        scatter_all(p.out, cid);
        return;
    }

    uint32_t sb0 = s2u(smraw);
    uint32_t sb = (sb0 + 1023) & ~1023u;
    char* sm = smraw + (sb - sb0);
    int lane = tid & 31, wid = tid >> 5;

    // npos (CTAs 0..7, warp 0 only; warp-shuffle reduction)
    if (cid < 8 && wid == 0) {
        int b = cid, cnt = 0;
        for (int s = 0; s < 16; s++) {
            float v = 0.f;
            #pragma unroll
            for (int j = 0; j < 8; j++)
                v += fabsf(p.extra[((size_t)b * 16 + s) * 704 + 448 + lane * 8 + j]);
            #pragma unroll
            for (int o = 16; o > 0; o >>= 1)
                v += __shfl_xor_sync(0xffffffff, v, o);
            if (v > 1e-6f) cnt++;
        }
        if (lane == 0) g_npos[b] = cnt;
    }

    // tile decode: 24 CTAs te1 (4 chains x 6 n-tiles), 40 CTAs te2 (4 x 10)
    int chain, nt, hid, nc_chain;
    if (cid < 24) { chain = cid / 6; nt = cid % 6; hid = 768; nc_chain = 6; }
    else { int c2 = cid - 24; chain = 4 + c2 / 10; nt = c2 % 10; hid = 1280; nc_chain = 10; }
    int te = chain >> 2, t = chain & 3;
    int n0 = nt * 128;
    int magic = (hid == 768) ? 2731 : 1639;
    float inv_gs = 1.f / (float)(hid >> 5);
    size_t co = ch_off(chain);

    float* st_s0 = g_sum + (0 * 8 + chain) * 4096; float* st_q0 = g_ss + (0 * 8 + chain) * 4096;
    float* st_s1 = g_sum + (1 * 8 + chain) * 4096; float* st_q1 = g_ss + (1 * 8 + chain) * 4096;
    float* st_s2 = g_sum + (2 * 8 + chain) * 4096; float* st_q2 = g_ss + (2 * 8 + chain) * 4096;
    int* cb = g_cbar + chain * 4;

    // s0: fc1 (K=704), extra -> bufA, stats -> slot0
    run_stage<0, true>(sm, sb, p.extra, g_bufA + co,
                       p.f1w[te] + (size_t)t * hid * 704, p.f1b[te] + t * hid,
                       nullptr, nullptr, nullptr, nullptr, st_s0, st_q0,
                       704, hid, n0, magic, inv_gs);
    barrier_on(cb + 0, nc_chain);

    // s1: block0, bufA -> bufB
    {
        size_t wo = (size_t)(t * 3 + 0) * hid;
        run_stage<1, true>(sm, sb, g_bufA + co, g_bufB + co,
                           p.bw[te] + wo * hid, p.bb[te] + wo,
                           p.gg[te] + wo, p.gb[te] + wo, st_s0, st_q0, st_s1, st_q1,
                           hid, hid, n0, magic, inv_gs);
    }
    barrier_on(cb + 1, nc_chain);

    // s2: block1, bufB -> bufA
    {
        size_t wo = (size_t)(t * 3 + 1) * hid;
        run_stage<1, true>(sm, sb, g_bufB + co, g_bufA + co,
                           p.bw[te] + wo * hid, p.bb[te] + wo,
                           p.gg[te] + wo, p.gb[te] + wo, st_s1, st_q1, st_s2, st_q2,
                           hid, hid, n0, magic, inv_gs);
    }
    barrier_on(cb + 2, nc_chain);

    // s3: block2, bufA -> bufB
    {
        size_t wo = (size_t)(t * 3 + 2) * hid;
        run_stage<1, false>(sm, sb, g_bufA + co, g_bufB + co,
                            p.bw[te] + wo * hid, p.bb[te] + wo,
                            p.gg[te] + wo, p.gb[te] + wo, st_s2, st_q2, nullptr, nullptr,
                            hid, hid, n0, magic, inv_gs);
    }
    barrier_on(cb + 3, nc_chain);

    // s4: out projection, bufB -> bufA (final tokens in bufA)
    run_stage<2, false>(sm, sb, g_bufB + co, g_bufA + co,
                        p.ow[te] + (size_t)t * hid * hid, p.ob[te] + t * hid,
                        nullptr, nullptr, nullptr, nullptr, nullptr, nullptr,
                        hid, hid, n0, magic, inv_gs);

    // join the big copy, then one global barrier, then scatter
    copy_work(p, &s_ticket);
    barrier_on(&g_gbar, NCTA);
    scatter_all(p.out, cid);
}

// ---------------- launch ----------------
extern "C" void kernel_launch(void* const* d_in, const int* in_sizes, int n_in,
                              void* d_out, int out_size) {
    Params p;
    p.e0    = (const float*)d_in[0];
    p.e1    = (const float*)d_in[1];
    p.e2    = (const float*)d_in[2];
    p.extra = (const float*)d_in[3];
    p.f1w[0] = (const float*)d_in[4];  p.f1b[0] = (const float*)d_in[5];
    p.gg[0]  = (const float*)d_in[6];  p.gb[0]  = (const float*)d_in[7];
    p.bw[0]  = (const float*)d_in[8];  p.bb[0]  = (const float*)d_in[9];
    p.ow[0]  = (const float*)d_in[10]; p.ob[0]  = (const float*)d_in[11];
    p.f1w[1] = (const float*)d_in[12]; p.f1b[1] = (const float*)d_in[13];
    p.bw[1]  = (const float*)d_in[16]; p.bb[1]  = (const float*)d_in[17];
    p.gg[1]  = (const float*)d_in[14]; p.gb[1]  = (const float*)d_in[15];
    p.ow[1]  = (const float*)d_in[18]; p.ob[1]  = (const float*)d_in[19];
    p.out = (float*)d_out;

    cudaFuncSetAttribute(mega_kernel, cudaFuncAttributeMaxDynamicSharedMemorySize, SMEM_BYTES);

    reset_kernel<<<(3 * 8 * 4096 + 255) / 256, 256>>>();
    mega_kernel<<<NCTA, NTHR, SMEM_BYTES>>>(p);
}

// round 8
// speedup vs baseline: 2.9219x; 1.0857x over previous
#include <cuda_runtime.h>
#include <cuda_bf16.h>
#include <math.h>
#include <stdint.h>

// ---------------- problem constants ----------------
#define SSV 4096
#define H1C 768
#define H2C 1280

static constexpr long OUT0_ELEMS = 8L * 4096L * 768L;
static constexpr long OUT1_ELEMS = 8L * 4096L * 1280L;
static constexpr long OUT2_ELEMS = 8L * 2816L;

static constexpr long N40 = OUT0_ELEMS / 4;
static constexpr long N41 = OUT1_ELEMS / 4;
static constexpr long N42 = OUT2_ELEMS / 4;
static constexpr long N4T = N40 + N41 + N42;

static constexpr int NCOMP = 128;    // compute CTAs: 128x128 tile, split-K=2
static constexpr int NCTA  = 148;
static constexpr int NTHR  = 512;
static constexpr int CHUNK4 = 16384;

static constexpr int BUFB = 32768;   // three 32KB buffers (chunk K=32)
static constexpr int SMEM_BYTES = 1024 + 3 * BUFB;

// ---------------- device globals ----------------
__device__ float g_bufA[1048576];
__device__ float g_bufB[1048576];
__device__ float g_part[1310720];       // [chain*10+nt][128][128] fp32 partials
__device__ float g_sum[3 * 8 * 4096];
__device__ float g_ss[3 * 8 * 4096];
__device__ int   g_mbar[400];           // merge barriers [(chain*10+nt)*5 + stage]
__device__ int   g_npos[8];
__device__ int   g_cbar[40];            // chain stage barriers [chain*5 + stage]
__device__ int   g_gbar;
__device__ int   g_ticket;

__device__ __forceinline__ size_t ch_off(int c) {
    return (c < 4) ? (size_t)c * 128 * 768
                   : (size_t)4 * 128 * 768 + (size_t)(c - 4) * 128 * 1280;
}

struct Params {
    const float* extra;
    const float* f1w[2]; const float* f1b[2];
    const float* gg[2];  const float* gb[2];
    const float* bw[2];  const float* bb[2];
    const float* ow[2];  const float* ob[2];
    const float* e0; const float* e1; const float* e2;
    float* out;
};

// ---------------- helpers ----------------
__device__ __forceinline__ uint32_t s2u(const void* p) {
    uint32_t a;
    asm("{ .reg .u64 t; cvta.to.shared.u64 t, %1; cvt.u32.u64 %0, t; }" : "=r"(a) : "l"(p));
    return a;
}
__device__ __forceinline__ uint32_t swz64(uint32_t o) { return o ^ ((o >> 3) & 0x30); }

__device__ __forceinline__ void ldsm4(uint32_t* r, uint32_t a) {
    asm volatile("ldmatrix.sync.aligned.m8n8.x4.shared.b16 {%0,%1,%2,%3}, [%4];"
                 : "=r"(r[0]), "=r"(r[1]), "=r"(r[2]), "=r"(r[3]) : "r"(a));
}
__device__ __forceinline__ void ldsm2(uint32_t* r, uint32_t a) {
    asm volatile("ldmatrix.sync.aligned.m8n8.x2.shared.b16 {%0,%1}, [%2];"
                 : "=r"(r[0]), "=r"(r[1]) : "r"(a));
}
__device__ __forceinline__ void mma16816(float* d, const uint32_t* a, const uint32_t* b) {
    asm volatile(
        "mma.sync.aligned.m16n8k16.row.col.f32.bf16.bf16.f32 "
        "{%0,%1,%2,%3}, {%4,%5,%6,%7}, {%8,%9}, {%0,%1,%2,%3};"
        : "+f"(d[0]), "+f"(d[1]), "+f"(d[2]), "+f"(d[3])
        : "r"(a[0]), "r"(a[1]), "r"(a[2]), "r"(a[3]), "r"(b[0]), "r"(b[1]));
}

// round-to-nearest hi/lo bf16 split (proven path from R5)
__device__ __forceinline__ void split2(float x0, float x1, uint32_t& h, uint32_t& l) {
    __nv_bfloat16 h0 = __float2bfloat16(x0);
    __nv_bfloat16 h1 = __float2bfloat16(x1);
    __nv_bfloat16 l0 = __float2bfloat16(x0 - __bfloat162float(h0));
    __nv_bfloat16 l1 = __float2bfloat16(x1 - __bfloat162float(h1));
    uint16_t hb0 = *reinterpret_cast<uint16_t*>(&h0);
    uint16_t hb1 = *reinterpret_cast<uint16_t*>(&h1);
    uint16_t lb0 = *reinterpret_cast<uint16_t*>(&l0);
    uint16_t lb1 = *reinterpret_cast<uint16_t*>(&l1);
    h = (uint32_t)hb0 | ((uint32_t)hb1 << 16);
    l = (uint32_t)lb0 | ((uint32_t)lb1 << 16);
}

__device__ __forceinline__ float4 ldcg4(const float* p) { return __ldcg((const float4*)p); }
__device__ __forceinline__ float2 ldcg2(const float* p) { return __ldcg((const float2*)p); }

// ---------------- barrier (fence + arrive + spin + fence) ----------------
__device__ __forceinline__ void barrier_on(int* cnt, int target) {
    __threadfence();
    __syncthreads();
    if (threadIdx.x == 0) {
        atomicAdd(cnt, 1);
        while (*(volatile int*)cnt < target) __nanosleep(32);
        __threadfence();
    }
    __syncthreads();
}

// ---------------- GEMM stage (split-K=2, triple-buffered pipeline) ----------------
template <int MODE, bool STATS>
__device__ void run_stage(char* sm, uint32_t sb,
                          const float* __restrict__ A, float* __restrict__ O,
                          const float* __restrict__ W, const float* __restrict__ bias,
                          const float* __restrict__ gng, const float* __restrict__ gnb,
                          const float* __restrict__ rs_s, const float* __restrict__ rs_q,
                          float* __restrict__ ws_s, float* __restrict__ ws_q,
                          int K, int Khalf, int kh0, int hid, int n0, int magic,
                          float inv_gs, float* __restrict__ part, int* mbar,
                          bool primary) {
    int tid = threadIdx.x, lane = tid & 31, wid = tid >> 5;
    int mbase = (wid & 3) * 32, nbase = (wid >> 2) * 32;
    int nch = Khalf >> 5;
    int row0 = tid >> 2;
    int cb8 = (tid & 3) * 8;

    const float* Arow = A + (size_t)row0 * K + kh0 + cb8;
    const float* Wrow = W + (size_t)(n0 + row0) * K + kh0 + cb8;
    uint32_t soff = swz64((uint32_t)row0 * 64 + (tid & 3) * 16);

    float acc[2][4][4];
    #pragma unroll
    for (int i = 0; i < 2; i++)
        #pragma unroll
        for (int j = 0; j < 4; j++)
            #pragma unroll
            for (int e = 0; e < 4; e++) acc[i][j][e] = 0.f;

    float4 ra[2], rw[2];

    auto convert_to = [&](char* buf, int cc) {
        float xs[8] = {ra[0].x, ra[0].y, ra[0].z, ra[0].w,
                       ra[1].x, ra[1].y, ra[1].z, ra[1].w};
        if (MODE == 1) {
            int k = kh0 + cc * 32 + cb8;
            int g = (k * magic) >> 16;
            float s = __ldg(rs_s + row0 * 32 + g);
            float q = __ldg(rs_q + row0 * 32 + g);
            float mean = s * inv_gs;
            float var = q * inv_gs - mean * mean;
            float rstd = rsqrtf(fmaxf(var, 0.f) + 1e-5f);
            #pragma unroll
            for (int e = 0; e < 8; e++)
                xs[e] = (xs[e] - mean) * rstd * __ldg(gng + k + e) + __ldg(gnb + k + e);
        }
        uint4 hv, lv;
        split2(xs[0], xs[1], hv.x, lv.x);
        split2(xs[2], xs[3], hv.y, lv.y);
        split2(xs[4], xs[5], hv.z, lv.z);
        split2(xs[6], xs[7], hv.w, lv.w);
        *(uint4*)(buf + soff)        = hv;
        *(uint4*)(buf + 8192 + soff) = lv;
        uint4 hw, lw;
        split2(rw[0].x, rw[0].y, hw.x, lw.x);
        split2(rw[0].z, rw[0].w, hw.y, lw.y);
        split2(rw[1].x, rw[1].y, hw.z, lw.z);
        split2(rw[1].z, rw[1].w, hw.w, lw.w);
        *(uint4*)(buf + 16384 + soff) = hw;
        *(uint4*)(buf + 24576 + soff) = lw;
    };
    auto load_regs = [&](int cc) {
        int kb = cc * 32;
        ra[0] = ldcg4(Arow + kb);
        ra[1] = ldcg4(Arow + kb + 4);
        rw[0] = __ldg((const float4*)(Wrow + kb));
        rw[1] = __ldg((const float4*)(Wrow + kb + 4));
    };

    load_regs(0);
    convert_to(sm, 0);
    load_regs(1);
    __syncthreads();

    for (int c = 0; c < nch; c++) {
        if (c + 1 < nch) {
            convert_to(sm + ((c + 1) % 3) * BUFB, c + 1);
            if (c + 2 < nch) load_regs(c + 2);
        }
        uint32_t bu = sb + (c % 3) * BUFB;
        #pragma unroll
        for (int ks = 0; ks < 2; ks++) {
            uint32_t ah[2][4], al[2][4], bh[4][2], bl[4][2];
            #pragma unroll
            for (int mt = 0; mt < 2; mt++) {
                uint32_t off = (uint32_t)(mbase + mt * 16 + (lane & 15)) * 64
                             + ks * 32 + (lane >> 4) * 16;
                ldsm4(ah[mt], bu + swz64(off));
                ldsm4(al[mt], bu + 8192 + swz64(off));
            }
            #pragma unroll
            for (int nt = 0; nt < 4; nt++) {
                uint32_t off = (uint32_t)(nbase + nt * 8 + (lane & 7)) * 64
                             + ks * 32 + ((lane >> 3) & 1) * 16;
                ldsm2(bh[nt], bu + 16384 + swz64(off));
                ldsm2(bl[nt], bu + 24576 + swz64(off));
            }
            #pragma unroll
            for (int mt = 0; mt < 2; mt++)
                #pragma unroll
                for (int nt = 0; nt < 4; nt++) {
                    mma16816(acc[mt][nt], ah[mt], bh[nt]);
                    mma16816(acc[mt][nt], al[mt], bh[nt]);
                    mma16816(acc[mt][nt], ah[mt], bl[nt]);
                }
        }
        __syncthreads();
    }

    // secondary publishes its partial before the rendezvous
    if (!primary) {
        #pragma unroll
        for (int mt = 0; mt < 2; mt++)
            #pragma unroll
            for (int nt = 0; nt < 4; nt++) {
                int cl = nbase + nt * 8 + (lane & 3) * 2;
                #pragma unroll
                for (int h = 0; h < 2; h++) {
                    int r = mbase + mt * 16 + (lane >> 2) + h * 8;
                    float2 v = {acc[mt][nt][h * 2], acc[mt][nt][h * 2 + 1]};
                    *(float2*)(part + r * 128 + cl) = v;
                }
            }
    }

    // 2-CTA merge rendezvous (proven barrier primitive: fence+count+fence)
    barrier_on(mbar, 2);
    if (!primary) return;

    // primary: merge + epilogue
    #pragma unroll
    for (int mt = 0; mt < 2; mt++)
        #pragma unroll
        for (int nt = 0; nt < 4; nt++) {
            int cl = nbase + nt * 8 + (lane & 3) * 2;
            int cc = n0 + cl;
            int gblk = ((n0 + nbase + nt * 8) * magic) >> 16;
            #pragma unroll
            for (int h = 0; h < 2; h++) {
                int r = mbase + mt * 16 + (lane >> 2) + h * 8;
                float2 pv = ldcg2(part + r * 128 + cl);
                float v0 = acc[mt][nt][h * 2 + 0] + pv.x + __ldg(bias + cc);
                float v1 = acc[mt][nt][h * 2 + 1] + pv.y + __ldg(bias + cc + 1);
                if (MODE <= 1) {
                    v0 = v0 / (1.f + __expf(-v0));
                    v1 = v1 / (1.f + __expf(-v1));
                }
                if (MODE == 1) {
                    float2 rv = ldcg2(A + (size_t)r * hid + cc);
                    v0 += rv.x; v1 += rv.y;
                }
                float2 o2 = {v0, v1};
                *(float2*)(O + (size_t)r * hid + cc) = o2;
                if (STATS) {
                    float ps = v0 + v1;
                    float q = v0 * v0 + v1 * v1;
                    ps += __shfl_xor_sync(0xffffffff, ps, 1);
                    q  += __shfl_xor_sync(0xffffffff, q, 1);
                    ps += __shfl_xor_sync(0xffffffff, ps, 2);
                    q  += __shfl_xor_sync(0xffffffff, q, 2);
                    if ((lane & 3) == 0) {
                        atomicAdd(ws_s + r * 32 + gblk, ps);
                        atomicAdd(ws_q + r * 32 + gblk, q);
                    }
                }
            }
        }
}

// ---------------- ticketed copy ----------------
__device__ void copy_work(const Params& p, int* s_ticket) {
    float4* o = (float4*)p.out;
    while (true) {
        if (threadIdx.x == 0) *s_ticket = atomicAdd(&g_ticket, 1);
        __syncthreads();
        long base = (long)(*s_ticket) * CHUNK4;
        __syncthreads();
        if (base >= N4T) break;
        const float4* src; long off;
        if (base < N40)            { src = (const float4*)p.e0; off = base; }
        else if (base < N40 + N41) { src = (const float4*)p.e1; off = base - N40; }
        else                       { src = (const float4*)p.e2; off = base - N40 - N41; }
        long end = base + CHUNK4;
        if (end > N4T) end = N4T;
        long n = end - base;
        #pragma unroll 4
        for (long i = threadIdx.x; i < n; i += NTHR)
            o[base + i] = src[off + i];
    }
}

// ---------------- scatter ----------------
__device__ void scatter_all(float* __restrict__ out, int cid) {
    for (int c = cid; c < 80; c += NCTA) {
        int te = c / 40, rem = c % 40, b = rem / 5, r = rem % 5;
        int np = g_npos[b];
        if (!np) continue;
        int hid = te ? H2C : H1C;
        int t = (r < 4) ? r : 3;
        int chain = te * 4 + t;
        const float* tok = g_bufA + ch_off(chain);
        float* o = te ? out + OUT0_ELEMS + (size_t)b * SSV * H2C
                      : out + (size_t)b * SSV * H1C;
        int h4 = hid >> 2, tot = np * h4;
        for (int e = threadIdx.x; e < tot; e += NTHR) {
            int i = e / h4, c4 = e % h4;
            int s = (r < 4) ? (SSV - 1 - r * np - i) : (SSV - 5 * np + i);
            float4 v = __ldcg((const float4*)(tok + (size_t)(b * 16 + i) * hid) + c4);
            ((float4*)(o + (size_t)s * hid))[c4] = v;
        }
    }
}

// ---------------- kernels ----------------
__global__ void reset_kernel() {
    int idx = blockIdx.x * 256 + threadIdx.x;
    if (idx < 3 * 8 * 4096) { g_sum[idx] = 0.f; g_ss[idx] = 0.f; }
    if (idx < 400) g_mbar[idx] = 0;
    if (idx < 40) g_cbar[idx] = 0;
    if (idx == 40) { g_gbar = 0; g_ticket = 0; }
}

__global__ void __launch_bounds__(NTHR, 1) mega_kernel(Params p) {
    extern __shared__ char smraw[];
    __shared__ int s_ticket;
    int cid = blockIdx.x, tid = threadIdx.x;

    if (cid >= NCOMP) {
        copy_work(p, &s_ticket);
        barrier_on(&g_gbar, NCTA);
        scatter_all(p.out, cid);
        return;
    }

    uint32_t sb0 = s2u(smraw);
    uint32_t sb = (sb0 + 1023) & ~1023u;
    char* sm = smraw + (sb - sb0);
    int lane = tid & 31, wid = tid >> 5;

    if (cid < 8 && wid == 0) {
        int b = cid, cnt = 0;
        for (int s = 0; s < 16; s++) {
            float v = 0.f;
            #pragma unroll
            for (int j = 0; j < 8; j++)
                v += fabsf(p.extra[((size_t)b * 16 + s) * 704 + 448 + lane * 8 + j]);
            #pragma unroll
            for (int o = 16; o > 0; o >>= 1)
                v += __shfl_xor_sync(0xffffffff, v, o);
            if (v > 1e-6f) cnt++;
        }
        if (lane == 0) g_npos[b] = cnt;
    }

    // decode: te1 = 48 CTAs (4 chains x 6 nt x 2 kh), te2 = 80 (4 x 10 x 2)
    int chain, nt, kh, hid, nc_chain;
    if (cid < 48) { chain = cid / 12; int r = cid % 12; nt = r % 6; kh = r / 6; hid = 768; nc_chain = 12; }
    else { int c2 = cid - 48; chain = 4 + c2 / 20; int r = c2 % 20; nt = r % 10; kh = r / 10; hid = 1280; nc_chain = 20; }
    int te = chain >> 2, t = chain & 3;
    int n0 = nt * 128;
    int magic = (hid == 768) ? 2731 : 1639;
    float inv_gs = 1.f / (float)(hid >> 5);
    size_t co = ch_off(chain);
    bool primary = (kh == 0);
    float* part = g_part + (size_t)(chain * 10 + nt) * 16384;
    int* mb = g_mbar + (chain * 10 + nt) * 5;
    int* cb = g_cbar + chain * 5;

    float* st_s0 = g_sum + (0 * 8 + chain) * 4096; float* st_q0 = g_ss + (0 * 8 + chain) * 4096;
    float* st_s1 = g_sum + (1 * 8 + chain) * 4096; float* st_q1 = g_ss + (1 * 8 + chain) * 4096;
    float* st_s2 = g_sum + (2 * 8 + chain) * 4096; float* st_q2 = g_ss + (2 * 8 + chain) * 4096;

    int Kh_fc1 = 352, Kh = hid >> 1;

    run_stage<0, true>(sm, sb, p.extra, g_bufA + co,
                       p.f1w[te] + (size_t)t * hid * 704, p.f1b[te] + t * hid,
                       nullptr, nullptr, nullptr, nullptr, st_s0, st_q0,
                       704, Kh_fc1, kh * Kh_fc1, hid, n0, magic, inv_gs,
                       part, mb + 0, primary);
    barrier_on(cb + 0, nc_chain);

    {
        size_t wo = (size_t)(t * 3 + 0) * hid;
        run_stage<1, true>(sm, sb, g_bufA + co, g_bufB + co,
                           p.bw[te] + wo * hid, p.bb[te] + wo,
                           p.gg[te] + wo, p.gb[te] + wo, st_s0, st_q0, st_s1, st_q1,
                           hid, Kh, kh * Kh, hid, n0, magic, inv_gs,
                           part, mb + 1, primary);
    }
    barrier_on(cb + 1, nc_chain);

    {
        size_t wo = (size_t)(t * 3 + 1) * hid;
        run_stage<1, true>(sm, sb, g_bufB + co, g_bufA + co,
                           p.bw[te] + wo * hid, p.bb[te] + wo,
                           p.gg[te] + wo, p.gb[te] + wo, st_s1, st_q1, st_s2, st_q2,
                           hid, Kh, kh * Kh, hid, n0, magic, inv_gs,
                           part, mb + 2, primary);
    }
    barrier_on(cb + 2, nc_chain);

    {
        size_t wo = (size_t)(t * 3 + 2) * hid;
        run_stage<1, false>(sm, sb, g_bufA + co, g_bufB + co,
                            p.bw[te] + wo * hid, p.bb[te] + wo,
                            p.gg[te] + wo, p.gb[te] + wo, st_s2, st_q2, nullptr, nullptr,
                            hid, Kh, kh * Kh, hid, n0, magic, inv_gs,
                            part, mb + 3, primary);
    }
    barrier_on(cb + 3, nc_chain);

    run_stage<2, false>(sm, sb, g_bufB + co, g_bufA + co,
                        p.ow[te] + (size_t)t * hid * hid, p.ob[te] + t * hid,
                        nullptr, nullptr, nullptr, nullptr, nullptr, nullptr,
                        hid, Kh, kh * Kh, hid, n0, magic, inv_gs,
                        part, mb + 4, primary);

    copy_work(p, &s_ticket);
    barrier_on(&g_gbar, NCTA);
    scatter_all(p.out, cid);
}

// ---------------- launch ----------------
extern "C" void kernel_launch(void* const* d_in, const int* in_sizes, int n_in,
                              void* d_out, int out_size) {
    Params p;
    p.e0    = (const float*)d_in[0];
    p.e1    = (const float*)d_in[1];
    p.e2    = (const float*)d_in[2];
    p.extra = (const float*)d_in[3];
    p.f1w[0] = (const float*)d_in[4];  p.f1b[0] = (const float*)d_in[5];
    p.gg[0]  = (const float*)d_in[6];  p.gb[0]  = (const float*)d_in[7];
    p.bw[0]  = (const float*)d_in[8];  p.bb[0]  = (const float*)d_in[9];
    p.ow[0]  = (const float*)d_in[10]; p.ob[0]  = (const float*)d_in[11];
    p.f1w[1] = (const float*)d_in[12]; p.f1b[1] = (const float*)d_in[13];
    p.gg[1]  = (const float*)d_in[14]; p.gb[1]  = (const float*)d_in[15];
    p.bw[1]  = (const float*)d_in[16]; p.bb[1]  = (const float*)d_in[17];
    p.ow[1]  = (const float*)d_in[18]; p.ob[1]  = (const float*)d_in[19];
    p.out = (float*)d_out;

    cudaFuncSetAttribute(mega_kernel, cudaFuncAttributeMaxDynamicSharedMemorySize, SMEM_BYTES);

    reset_kernel<<<(3 * 8 * 4096 + 255) / 256, 256>>>();
    mega_kernel<<<NCTA, NTHR, SMEM_BYTES>>>(p);
}

// round 9
// speedup vs baseline: 2.9950x; 1.0250x over previous
#include <cuda_runtime.h>
#include <cuda_bf16.h>
#include <math.h>
#include <stdint.h>

// ---------------- problem constants ----------------
#define SSV 4096
#define H1C 768
#define H2C 1280

static constexpr long OUT0_ELEMS = 8L * 4096L * 768L;
static constexpr long OUT1_ELEMS = 8L * 4096L * 1280L;
static constexpr long OUT2_ELEMS = 8L * 2816L;

static constexpr long N40 = OUT0_ELEMS / 4;
static constexpr long N41 = OUT1_ELEMS / 4;
static constexpr long N42 = OUT2_ELEMS / 4;
static constexpr long N4T = N40 + N41 + N42;

static constexpr int NCOMP = 256;     // compute CTAs (2/SM): M64xN128 tile, split-K=2
static constexpr int NCTA  = 296;
static constexpr int NTHR  = 256;
static constexpr int CHUNK4 = 16384;

// per-buffer: Ah[64x32]=4K @0, Al @4096, Wh[128x32]=8K @8192, Wl @16384 -> 24KB
static constexpr int BUFB = 24576;
static constexpr int SMEM_BYTES = 1024 + 3 * BUFB;   // 74752; x2 CTAs = 146KB/SM

// ---------------- device globals ----------------
__device__ float g_bufA[1048576];
__device__ float g_bufB[1048576];
__device__ float g_part[1048576];       // 128 slots x 64x128 fp32 partials
__device__ float g_sum[3 * 8 * 4096];
__device__ float g_ss[3 * 8 * 4096];
__device__ int   g_mbar[640];           // merge barriers [slot*5 + stage]
__device__ int   g_npos[8];
__device__ int   g_cbar[40];            // chain stage barriers [chain*5 + stage]
__device__ int   g_gbar;
__device__ int   g_ticket;

__device__ __forceinline__ size_t ch_off(int c) {
    return (c < 4) ? (size_t)c * 128 * 768
                   : (size_t)4 * 128 * 768 + (size_t)(c - 4) * 128 * 1280;
}

struct Params {
    const float* extra;
    const float* f1w[2]; const float* f1b[2];
    const float* gg[2];  const float* gb[2];
    const float* bw[2];  const float* bb[2];
    const float* ow[2];  const float* ob[2];
    const float* e0; const float* e1; const float* e2;
    float* out;
};

// ---------------- helpers ----------------
__device__ __forceinline__ uint32_t s2u(const void* p) {
    uint32_t a;
    asm("{ .reg .u64 t; cvta.to.shared.u64 t, %1; cvt.u32.u64 %0, t; }" : "=r"(a) : "l"(p));
    return a;
}
__device__ __forceinline__ uint32_t swz64(uint32_t o) { return o ^ ((o >> 3) & 0x30); }

__device__ __forceinline__ void ldsm4(uint32_t* r, uint32_t a) {
    asm volatile("ldmatrix.sync.aligned.m8n8.x4.shared.b16 {%0,%1,%2,%3}, [%4];"
                 : "=r"(r[0]), "=r"(r[1]), "=r"(r[2]), "=r"(r[3]) : "r"(a));
}
__device__ __forceinline__ void ldsm2(uint32_t* r, uint32_t a) {
    asm volatile("ldmatrix.sync.aligned.m8n8.x2.shared.b16 {%0,%1}, [%2];"
                 : "=r"(r[0]), "=r"(r[1]) : "r"(a));
}
__device__ __forceinline__ void mma16816(float* d, const uint32_t* a, const uint32_t* b) {
    asm volatile(
        "mma.sync.aligned.m16n8k16.row.col.f32.bf16.bf16.f32 "
        "{%0,%1,%2,%3}, {%4,%5,%6,%7}, {%8,%9}, {%0,%1,%2,%3};"
        : "+f"(d[0]), "+f"(d[1]), "+f"(d[2]), "+f"(d[3])
        : "r"(a[0]), "r"(a[1]), "r"(a[2]), "r"(a[3]), "r"(b[0]), "r"(b[1]));
}

// round-to-nearest hi/lo bf16 split
__device__ __forceinline__ void split2(float x0, float x1, uint32_t& h, uint32_t& l) {
    __nv_bfloat16 h0 = __float2bfloat16(x0);
    __nv_bfloat16 h1 = __float2bfloat16(x1);
    __nv_bfloat16 l0 = __float2bfloat16(x0 - __bfloat162float(h0));
    __nv_bfloat16 l1 = __float2bfloat16(x1 - __bfloat162float(h1));
    uint16_t hb0 = *reinterpret_cast<uint16_t*>(&h0);
    uint16_t hb1 = *reinterpret_cast<uint16_t*>(&h1);
    uint16_t lb0 = *reinterpret_cast<uint16_t*>(&l0);
    uint16_t lb1 = *reinterpret_cast<uint16_t*>(&l1);
    h = (uint32_t)hb0 | ((uint32_t)hb1 << 16);
    l = (uint32_t)lb0 | ((uint32_t)lb1 << 16);
}

__device__ __forceinline__ float4 ldcg4(const float* p) { return __ldcg((const float4*)p); }
__device__ __forceinline__ float2 ldcg2(const float* p) { return __ldcg((const float2*)p); }

// ---------------- barrier (fence + arrive + spin + fence) ----------------
__device__ __forceinline__ void barrier_on(int* cnt, int target) {
    __threadfence();
    __syncthreads();
    if (threadIdx.x == 0) {
        atomicAdd(cnt, 1);
        while (*(volatile int*)cnt < target) __nanosleep(32);
        __threadfence();
    }
    __syncthreads();
}

// ---------------- GEMM stage: M64xN128 tile, split-K=2, triple-buffered ----------------
// Pointers pre-offset by caller: A += m0*K, O += m0*hid, rs/ws += m0*32.
template <int MODE, bool STATS>
__device__ void run_stage(char* sm, uint32_t sb,
                          const float* __restrict__ A, float* __restrict__ O,
                          const float* __restrict__ W, const float* __restrict__ bias,
                          const float* __restrict__ gng, const float* __restrict__ gnb,
                          const float* __restrict__ rs_s, const float* __restrict__ rs_q,
                          float* __restrict__ ws_s, float* __restrict__ ws_q,
                          int K, int Khalf, int kh0, int hid, int n0, int magic,
                          float inv_gs, float* __restrict__ part, int* mbar,
                          bool primary) {
    int tid = threadIdx.x, lane = tid & 31, wid = tid >> 5;
    int mbase = (wid & 1) * 32, nbase = (wid >> 1) * 32;
    int nch = Khalf >> 5;

    // A loader: 64 rows, 4 threads/row, 8 cols each
    int rowa = tid >> 2, ca8 = (tid & 3) * 8;
    // W loader: 128 rows, 2 threads/row, 16 cols each
    int roww = tid >> 1, cw16 = (tid & 1) * 16;

    const float* Arow = A + (size_t)rowa * K + kh0 + ca8;
    const float* Wrow = W + (size_t)(n0 + roww) * K + kh0 + cw16;
    uint32_t soffA  = swz64((uint32_t)rowa * 64 + (tid & 3) * 16);
    uint32_t soffW0 = swz64((uint32_t)roww * 64 + (tid & 1) * 32);
    uint32_t soffW1 = swz64((uint32_t)roww * 64 + (tid & 1) * 32 + 16);

    float acc[2][4][4];
    #pragma unroll
    for (int i = 0; i < 2; i++)
        #pragma unroll
        for (int j = 0; j < 4; j++)
            #pragma unroll
            for (int e = 0; e < 4; e++) acc[i][j][e] = 0.f;

    float4 ra[2], rw[4];

    auto convert_to = [&](char* buf, int cc) {
        float xs[8] = {ra[0].x, ra[0].y, ra[0].z, ra[0].w,
                       ra[1].x, ra[1].y, ra[1].z, ra[1].w};
        if (MODE == 1) {
            int k = kh0 + cc * 32 + ca8;
            int g = (k * magic) >> 16;
            float s = __ldg(rs_s + rowa * 32 + g);
            float q = __ldg(rs_q + rowa * 32 + g);
            float mean = s * inv_gs;
            float var = q * inv_gs - mean * mean;
            float rstd = rsqrtf(fmaxf(var, 0.f) + 1e-5f);
            #pragma unroll
            for (int e = 0; e < 8; e++)
                xs[e] = (xs[e] - mean) * rstd * __ldg(gng + k + e) + __ldg(gnb + k + e);
        }
        uint4 hv, lv;
        split2(xs[0], xs[1], hv.x, lv.x);
        split2(xs[2], xs[3], hv.y, lv.y);
        split2(xs[4], xs[5], hv.z, lv.z);
        split2(xs[6], xs[7], hv.w, lv.w);
        *(uint4*)(buf + soffA)        = hv;
        *(uint4*)(buf + 4096 + soffA) = lv;

        uint4 hw, lw;
        split2(rw[0].x, rw[0].y, hw.x, lw.x);
        split2(rw[0].z, rw[0].w, hw.y, lw.y);
        split2(rw[1].x, rw[1].y, hw.z, lw.z);
        split2(rw[1].z, rw[1].w, hw.w, lw.w);
        *(uint4*)(buf + 8192 + soffW0)  = hw;
        *(uint4*)(buf + 16384 + soffW0) = lw;
        split2(rw[2].x, rw[2].y, hw.x, lw.x);
        split2(rw[2].z, rw[2].w, hw.y, lw.y);
        split2(rw[3].x, rw[3].y, hw.z, lw.z);
        split2(rw[3].z, rw[3].w, hw.w, lw.w);
        *(uint4*)(buf + 8192 + soffW1)  = hw;
        *(uint4*)(buf + 16384 + soffW1) = lw;
    };
    auto load_regs = [&](int cc) {
        int kb = cc * 32;
        ra[0] = ldcg4(Arow + kb);
        ra[1] = ldcg4(Arow + kb + 4);
        rw[0] = __ldg((const float4*)(Wrow + kb));
        rw[1] = __ldg((const float4*)(Wrow + kb + 4));
        rw[2] = __ldg((const float4*)(Wrow + kb + 8));
        rw[3] = __ldg((const float4*)(Wrow + kb + 12));
    };

    load_regs(0);
    convert_to(sm, 0);
    load_regs(1);
    __syncthreads();

    for (int c = 0; c < nch; c++) {
        if (c + 1 < nch) {
            convert_to(sm + ((c + 1) % 3) * BUFB, c + 1);
            if (c + 2 < nch) load_regs(c + 2);
        }
        uint32_t bu = sb + (c % 3) * BUFB;
        #pragma unroll
        for (int ks = 0; ks < 2; ks++) {
            uint32_t ah[2][4], al[2][4], bh[4][2], bl[4][2];
            #pragma unroll
            for (int mt = 0; mt < 2; mt++) {
                uint32_t off = (uint32_t)(mbase + mt * 16 + (lane & 15)) * 64
                             + ks * 32 + (lane >> 4) * 16;
                ldsm4(ah[mt], bu + swz64(off));
                ldsm4(al[mt], bu + 4096 + swz64(off));
            }
            #pragma unroll
            for (int nt = 0; nt < 4; nt++) {
                uint32_t off = (uint32_t)(nbase + nt * 8 + (lane & 7)) * 64
                             + ks * 32 + ((lane >> 3) & 1) * 16;
                ldsm2(bh[nt], bu + 8192 + swz64(off));
                ldsm2(bl[nt], bu + 16384 + swz64(off));
            }
            #pragma unroll
            for (int mt = 0; mt < 2; mt++)
                #pragma unroll
                for (int nt = 0; nt < 4; nt++) {
                    mma16816(acc[mt][nt], ah[mt], bh[nt]);
                    mma16816(acc[mt][nt], al[mt], bh[nt]);
                    mma16816(acc[mt][nt], ah[mt], bl[nt]);
                }
        }
        __syncthreads();
    }

    if (!primary) {
        #pragma unroll
        for (int mt = 0; mt < 2; mt++)
            #pragma unroll
            for (int nt = 0; nt < 4; nt++) {
                int cl = nbase + nt * 8 + (lane & 3) * 2;
                #pragma unroll
                for (int h = 0; h < 2; h++) {
                    int r = mbase + mt * 16 + (lane >> 2) + h * 8;
                    float2 v = {acc[mt][nt][h * 2], acc[mt][nt][h * 2 + 1]};
                    *(float2*)(part + r * 128 + cl) = v;
                }
            }
    }

    barrier_on(mbar, 2);
    if (!primary) return;

    #pragma unroll
    for (int mt = 0; mt < 2; mt++)
        #pragma unroll
        for (int nt = 0; nt < 4; nt++) {
            int cl = nbase + nt * 8 + (lane & 3) * 2;
            int cc = n0 + cl;
            int gblk = ((n0 + nbase + nt * 8) * magic) >> 16;
            #pragma unroll
            for (int h = 0; h < 2; h++) {
                int r = mbase + mt * 16 + (lane >> 2) + h * 8;
                float2 pv = ldcg2(part + r * 128 + cl);
                float v0 = acc[mt][nt][h * 2 + 0] + pv.x + __ldg(bias + cc);
                float v1 = acc[mt][nt][h * 2 + 1] + pv.y + __ldg(bias + cc + 1);
                if (MODE <= 1) {
                    v0 = v0 / (1.f + __expf(-v0));
                    v1 = v1 / (1.f + __expf(-v1));
                }
                if (MODE == 1) {
                    float2 rv = ldcg2(A + (size_t)r * hid + cc);
                    v0 += rv.x; v1 += rv.y;
                }
                float2 o2 = {v0, v1};
                *(float2*)(O + (size_t)r * hid + cc) = o2;
                if (STATS) {
                    float ps = v0 + v1;
                    float q = v0 * v0 + v1 * v1;
                    ps += __shfl_xor_sync(0xffffffff, ps, 1);
                    q  += __shfl_xor_sync(0xffffffff, q, 1);
                    ps += __shfl_xor_sync(0xffffffff, ps, 2);
                    q  += __shfl_xor_sync(0xffffffff, q, 2);
                    if ((lane & 3) == 0) {
                        atomicAdd(ws_s + r * 32 + gblk, ps);
                        atomicAdd(ws_q + r * 32 + gblk, q);
                    }
                }
            }
        }
}

// ---------------- ticketed copy ----------------
__device__ void copy_work(const Params& p, int* s_ticket) {
    float4* o = (float4*)p.out;
    while (true) {
        if (threadIdx.x == 0) *s_ticket = atomicAdd(&g_ticket, 1);
        __syncthreads();
        long base = (long)(*s_ticket) * CHUNK4;
        __syncthreads();
        if (base >= N4T) break;
        const float4* src; long off;
        if (base < N40)            { src = (const float4*)p.e0; off = base; }
        else if (base < N40 + N41) { src = (const float4*)p.e1; off = base - N40; }
        else                       { src = (const float4*)p.e2; off = base - N40 - N41; }
        long end = base + CHUNK4;
        if (end > N4T) end = N4T;
        long n = end - base;
        #pragma unroll 4
        for (long i = threadIdx.x; i < n; i += NTHR)
            o[base + i] = src[off + i];
    }
}

// ---------------- scatter ----------------
__device__ void scatter_all(float* __restrict__ out, int cid) {
    for (int c = cid; c < 80; c += NCTA) {
        int te = c / 40, rem = c % 40, b = rem / 5, r = rem % 5;
        int np = g_npos[b];
        if (!np) continue;
        int hid = te ? H2C : H1C;
        int t = (r < 4) ? r : 3;
        int chain = te * 4 + t;
        const float* tok = g_bufA + ch_off(chain);
        float* o = te ? out + OUT0_ELEMS + (size_t)b * SSV * H2C
                      : out + (size_t)b * SSV * H1C;
        int h4 = hid >> 2, tot = np * h4;
        for (int e = threadIdx.x; e < tot; e += NTHR) {
            int i = e / h4, c4 = e % h4;
            int s = (r < 4) ? (SSV - 1 - r * np - i) : (SSV - 5 * np + i);
            float4 v = __ldcg((const float4*)(tok + (size_t)(b * 16 + i) * hid) + c4);
            ((float4*)(o + (size_t)s * hid))[c4] = v;
        }
    }
}

// ---------------- kernels ----------------
__global__ void reset_kernel() {
    int idx = blockIdx.x * 256 + threadIdx.x;
    if (idx < 3 * 8 * 4096) { g_sum[idx] = 0.f; g_ss[idx] = 0.f; }
    if (idx < 640) g_mbar[idx] = 0;
    if (idx < 40) g_cbar[idx] = 0;
    if (idx == 40) { g_gbar = 0; g_ticket = 0; }
}

__global__ void __launch_bounds__(NTHR, 2) mega_kernel(Params p) {
    extern __shared__ char smraw[];
    __shared__ int s_ticket;
    int cid = blockIdx.x, tid = threadIdx.x;

    if (cid >= NCOMP) {
        copy_work(p, &s_ticket);
        barrier_on(&g_gbar, NCTA);
        scatter_all(p.out, cid);
        return;
    }

    uint32_t sb0 = s2u(smraw);
    uint32_t sb = (sb0 + 1023) & ~1023u;
    char* sm = smraw + (sb - sb0);
    int lane = tid & 31, wid = tid >> 5;

    if (cid < 8 && wid == 0) {
        int b = cid, cnt = 0;
        for (int s = 0; s < 16; s++) {
            float v = 0.f;
            #pragma unroll
            for (int j = 0; j < 8; j++)
                v += fabsf(p.extra[((size_t)b * 16 + s) * 704 + 448 + lane * 8 + j]);
            #pragma unroll
            for (int o = 16; o > 0; o >>= 1)
                v += __shfl_xor_sync(0xffffffff, v, o);
            if (v > 1e-6f) cnt++;
        }
        if (lane == 0) g_npos[b] = cnt;
    }

    // decode: cid<160: te2 chains (4 x 40: kh x mt x nt = 2x2x10)
    //         160<=cid<256: te1 chains (4 x 24: 2x2x6)
    int chain, nt, mt, kh, hid, nc_chain, slot;
    if (cid < 160) {
        chain = 4 + cid / 40;
        int r = cid % 40;
        kh = r / 20; int rr = r % 20;
        mt = rr / 10; nt = rr % 10;
        hid = 1280; nc_chain = 40;
        slot = 48 + (chain - 4) * 20 + mt * 10 + nt;
    } else {
        int c2 = cid - 160;
        chain = c2 / 24;
        int r = c2 % 24;
        kh = r / 12; int rr = r % 12;
        mt = rr / 6; nt = rr % 6;
        hid = 768; nc_chain = 24;
        slot = chain * 12 + mt * 6 + nt;
    }
    int te = chain >> 2, t = chain & 3;
    int n0 = nt * 128, m0 = mt * 64;
    int magic = (hid == 768) ? 2731 : 1639;
    float inv_gs = 1.f / (float)(hid >> 5);
    size_t co = ch_off(chain);
    bool primary = (kh == 0);
    float* part = g_part + (size_t)slot * 8192;
    int* mb = g_mbar + slot * 5;
    int* cb = g_cbar + chain * 5;

    float* st_s0 = g_sum + (0 * 8 + chain) * 4096 + m0 * 32;
    float* st_q0 = g_ss  + (0 * 8 + chain) * 4096 + m0 * 32;
    float* st_s1 = g_sum + (1 * 8 + chain) * 4096 + m0 * 32;
    float* st_q1 = g_ss  + (1 * 8 + chain) * 4096 + m0 * 32;
    float* st_s2 = g_sum + (2 * 8 + chain) * 4096 + m0 * 32;
    float* st_q2 = g_ss  + (2 * 8 + chain) * 4096 + m0 * 32;

    int Kh_fc1 = 352, Kh = hid >> 1;
    float* bA = g_bufA + co + (size_t)m0 * hid;
    float* bB = g_bufB + co + (size_t)m0 * hid;

    run_stage<0, true>(sm, sb, p.extra + (size_t)m0 * 704, bA,
                       p.f1w[te] + (size_t)t * hid * 704, p.f1b[te] + t * hid,
                       nullptr, nullptr, nullptr, nullptr, st_s0, st_q0,
                       704, Kh_fc1, kh * Kh_fc1, hid, n0, magic, inv_gs,
                       part, mb + 0, primary);
    barrier_on(cb + 0, nc_chain);

    {
        size_t wo = (size_t)(t * 3 + 0) * hid;
        run_stage<1, true>(sm, sb, bA, bB,
                           p.bw[te] + wo * hid, p.bb[te] + wo,
                           p.gg[te] + wo, p.gb[te] + wo, st_s0, st_q0, st_s1, st_q1,
                           hid, Kh, kh * Kh, hid, n0, magic, inv_gs,
                           part, mb + 1, primary);
    }
    barrier_on(cb + 1, nc_chain);

    {
        size_t wo = (size_t)(t * 3 + 1) * hid;
        run_stage<1, true>(sm, sb, bB, bA,
                           p.bw[te] + wo * hid, p.bb[te] + wo,
                           p.gg[te] + wo, p.gb[te] + wo, st_s1, st_q1, st_s2, st_q2,
                           hid, Kh, kh * Kh, hid, n0, magic, inv_gs,
                           part, mb + 2, primary);
    }
    barrier_on(cb + 2, nc_chain);

    {
        size_t wo = (size_t)(t * 3 + 2) * hid;
        run_stage<1, false>(sm, sb, bA, bB,
                            p.bw[te] + wo * hid, p.bb[te] + wo,
                            p.gg[te] + wo, p.gb[te] + wo, st_s2, st_q2, nullptr, nullptr,
                            hid, Kh, kh * Kh, hid, n0, magic, inv_gs,
                            part, mb + 3, primary);
    }
    barrier_on(cb + 3, nc_chain);

    run_stage<2, false>(sm, sb, bB, bA,
                        p.ow[te] + (size_t)t * hid * hid, p.ob[te] + t * hid,
                        nullptr, nullptr, nullptr, nullptr, nullptr, nullptr,
                        hid, Kh, kh * Kh, hid, n0, magic, inv_gs,
                        part, mb + 4, primary);

    copy_work(p, &s_ticket);
    barrier_on(&g_gbar, NCTA);
    scatter_all(p.out, cid);
}

// ---------------- launch ----------------
extern "C" void kernel_launch(void* const* d_in, const int* in_sizes, int n_in,
                              void* d_out, int out_size) {
    Params p;
    p.e0    = (const float*)d_in[0];
    p.e1    = (const float*)d_in[1];
    p.e2    = (const float*)d_in[2];
    p.extra = (const float*)d_in[3];
    p.f1w[0] = (const float*)d_in[4];  p.f1b[0] = (const float*)d_in[5];
    p.gg[0]  = (const float*)d_in[6];  p.gb[0]  = (const float*)d_in[7];
    p.bw[0]  = (const float*)d_in[8];  p.bb[0]  = (const float*)d_in[9];
    p.ow[0]  = (const float*)d_in[10]; p.ob[0]  = (const float*)d_in[11];
    p.f1w[1] = (const float*)d_in[12]; p.f1b[1] = (const float*)d_in[13];
    p.gg[1]  = (const float*)d_in[14]; p.gb[1]  = (const float*)d_in[15];
    p.bw[1]  = (const float*)d_in[16]; p.bb[1]  = (const float*)d_in[17];
    p.ow[1]  = (const float*)d_in[18]; p.ob[1]  = (const float*)d_in[19];
    p.out = (float*)d_out;

    cudaFuncSetAttribute(mega_kernel, cudaFuncAttributeMaxDynamicSharedMemorySize, SMEM_BYTES);

    reset_kernel<<<(3 * 8 * 4096 + 255) / 256, 256>>>();
    mega_kernel<<<NCTA, NTHR, SMEM_BYTES>>>(p);
}

// round 13
// speedup vs baseline: 3.0619x; 1.0224x over previous
#include <cuda_runtime.h>
#include <cuda_bf16.h>
#include <math.h>
#include <stdint.h>

// ---------------- problem constants ----------------
#define SSV 4096
#define H1C 768
#define H2C 1280

static constexpr long OUT0_ELEMS = 8L * 4096L * 768L;
static constexpr long OUT1_ELEMS = 8L * 4096L * 1280L;
static constexpr long OUT2_ELEMS = 8L * 2816L;

static constexpr long N40 = OUT0_ELEMS / 4;
static constexpr long N41 = OUT1_ELEMS / 4;
static constexpr long N42 = OUT2_ELEMS / 4;
static constexpr long N4T = N40 + N41 + N42;

static constexpr int NCOMP = 256;     // compute CTAs (2/SM): M64xN128 tile, split-K=2
static constexpr int NCTA  = 296;
static constexpr int NTHR  = 256;
static constexpr long SLOT4 = 1024;   // float4 per copy ticket (16KB)

// per-buffer: Ah[64x32]=4K @0, Al @4096, Wh[128x32]=8K @8192, Wl @16384 -> 24KB
static constexpr int BUFB = 24576;
static constexpr int SMEM_BYTES = 1024 + 3 * BUFB;

// ---------------- device globals ----------------
__device__ float g_bufA[1048576];
__device__ float g_bufB[1048576];
__device__ float g_part[1048576];       // 128 slots x 64x128 fp32 partials
__device__ float g_sum[3 * 8 * 4096];
__device__ float g_ss[3 * 8 * 4096];
__device__ int   g_mbar[640];           // merge barriers [slot*5 + stage]
__device__ int   g_npos[8];
__device__ int   g_cbar[40];            // chain stage barriers [chain*5 + stage]
__device__ int   g_gbar;
__device__ int   g_ticket;

__device__ __forceinline__ size_t ch_off(int c) {
    return (c < 4) ? (size_t)c * 128 * 768
                   : (size_t)4 * 128 * 768 + (size_t)(c - 4) * 128 * 1280;
}

struct Params {
    const float* extra;
    const float* f1w[2]; const float* f1b[2];
    const float* gg[2];  const float* gb[2];
    const float* bw[2];  const float* bb[2];
    const float* ow[2];  const float* ob[2];
    const float* e0; const float* e1; const float* e2;
    float* out;
};

// ---------------- helpers ----------------
__device__ __forceinline__ uint32_t s2u(const void* p) {
    uint32_t a;
    asm("{ .reg .u64 t; cvta.to.shared.u64 t, %1; cvt.u32.u64 %0, t; }" : "=r"(a) : "l"(p));
    return a;
}
__device__ __forceinline__ uint32_t swz64(uint32_t o) { return o ^ ((o >> 3) & 0x30); }

__device__ __forceinline__ void ldsm4(uint32_t* r, uint32_t a) {
    asm volatile("ldmatrix.sync.aligned.m8n8.x4.shared.b16 {%0,%1,%2,%3}, [%4];"
                 : "=r"(r[0]), "=r"(r[1]), "=r"(r[2]), "=r"(r[3]) : "r"(a));
}
__device__ __forceinline__ void ldsm2(uint32_t* r, uint32_t a) {
    asm volatile("ldmatrix.sync.aligned.m8n8.x2.shared.b16 {%0,%1}, [%2];"
                 : "=r"(r[0]), "=r"(r[1]) : "r"(a));
}
__device__ __forceinline__ void mma16816(float* d, const uint32_t* a, const uint32_t* b) {
    asm volatile(
        "mma.sync.aligned.m16n8k16.row.col.f32.bf16.bf16.f32 "
        "{%0,%1,%2,%3}, {%4,%5,%6,%7}, {%8,%9}, {%0,%1,%2,%3};"
        : "+f"(d[0]), "+f"(d[1]), "+f"(d[2]), "+f"(d[3])
        : "r"(a[0]), "r"(a[1]), "r"(a[2]), "r"(a[3]), "r"(b[0]), "r"(b[1]));
}

// round-to-nearest hi/lo bf16 split (R9-proven)
__device__ __forceinline__ void split2(float x0, float x1, uint32_t& h, uint32_t& l) {
    __nv_bfloat16 h0 = __float2bfloat16(x0);
    __nv_bfloat16 h1 = __float2bfloat16(x1);
    __nv_bfloat16 l0 = __float2bfloat16(x0 - __bfloat162float(h0));
    __nv_bfloat16 l1 = __float2bfloat16(x1 - __bfloat162float(h1));
    uint16_t hb0 = *reinterpret_cast<uint16_t*>(&h0);
    uint16_t hb1 = *reinterpret_cast<uint16_t*>(&h1);
    uint16_t lb0 = *reinterpret_cast<uint16_t*>(&l0);
    uint16_t lb1 = *reinterpret_cast<uint16_t*>(&l1);
    h = (uint32_t)hb0 | ((uint32_t)hb1 << 16);
    l = (uint32_t)lb0 | ((uint32_t)lb1 << 16);
}

__device__ __forceinline__ float4 ldcg4(const float* p) { return __ldcg((const float4*)p); }
__device__ __forceinline__ float2 ldcg2(const float* p) { return __ldcg((const float2*)p); }

// ---------------- barrier (fence + arrive + spin + fence) ----------------
__device__ __forceinline__ void barrier_on(int* cnt, int target) {
    __threadfence();
    __syncthreads();
    if (threadIdx.x == 0) {
        atomicAdd(cnt, 1);
        while (*(volatile int*)cnt < target) __nanosleep(32);
        __threadfence();
    }
    __syncthreads();
}

// ---------------- copy one 16KB ticket (1024 float4, 4/thread) ----------------
__device__ __forceinline__ void copy_slot(const Params& p, long tk) {
    long base = tk * SLOT4;
    if (base >= N4T) return;
    long i0 = base + threadIdx.x * 4;
    const float4* src; long off;
    if (base < N40)            { src = (const float4*)p.e0; off = i0; }
    else if (base < N40 + N41) { src = (const float4*)p.e1; off = i0 - N40; }
    else                       { src = (const float4*)p.e2; off = i0 - N40 - N41; }
    float4* o = (float4*)p.out;
    #pragma unroll
    for (int e = 0; e < 4; e++) {
        long idx = i0 + e;
        if (idx < N4T) o[idx] = __ldcg(src + off + e);
    }
}

// ---------------- GEMM stage: M64xN128, split-K=2, bf16x3, triple-buffered ----------------
// EXACT R9 compute; adds one copy-ticket per K-chunk (overlap with MMA stalls).
// Pointers pre-offset by caller: A += m0*K, O += m0*hid, rs/ws += m0*32.
template <int MODE, bool STATS>
__device__ void run_stage(char* sm, uint32_t sb,
                          const float* __restrict__ A, float* __restrict__ O,
                          const float* __restrict__ W, const float* __restrict__ bias,
                          const float* __restrict__ gng, const float* __restrict__ gnb,
                          const float* __restrict__ rs_s, const float* __restrict__ rs_q,
                          float* __restrict__ ws_s, float* __restrict__ ws_q,
                          int K, int Khalf, int kh0, int hid, int n0, int magic,
                          float inv_gs, float* __restrict__ part, int* mbar,
                          bool primary, const Params& pp, int* s_t2) {
    int tid = threadIdx.x, lane = tid & 31, wid = tid >> 5;
    int mbase = (wid & 1) * 32, nbase = (wid >> 1) * 32;
    int nch = Khalf >> 5;

    // A loader: 64 rows, 4 threads/row, 8 cols each
    int rowa = tid >> 2, ca8 = (tid & 3) * 8;
    // W loader: 128 rows, 2 threads/row, 16 cols each
    int roww = tid >> 1, cw16 = (tid & 1) * 16;

    const float* Arow = A + (size_t)rowa * K + kh0 + ca8;
    const float* Wrow = W + (size_t)(n0 + roww) * K + kh0 + cw16;
    uint32_t soffA  = swz64((uint32_t)rowa * 64 + (tid & 3) * 16);
    uint32_t soffW0 = swz64((uint32_t)roww * 64 + (tid & 1) * 32);
    uint32_t soffW1 = swz64((uint32_t)roww * 64 + (tid & 1) * 32 + 16);

    float acc[2][4][4];
    #pragma unroll
    for (int i = 0; i < 2; i++)
        #pragma unroll
        for (int j = 0; j < 4; j++)
            #pragma unroll
            for (int e = 0; e < 4; e++) acc[i][j][e] = 0.f;

    float4 ra[2], rw[4];

    auto convert_to = [&](char* buf, int cc) {
        float xs[8] = {ra[0].x, ra[0].y, ra[0].z, ra[0].w,
                       ra[1].x, ra[1].y, ra[1].z, ra[1].w};
        if (MODE == 1) {
            int k = kh0 + cc * 32 + ca8;
            int g = (k * magic) >> 16;
            float s = __ldg(rs_s + rowa * 32 + g);
            float q = __ldg(rs_q + rowa * 32 + g);
            float mean = s * inv_gs;
            float var = q * inv_gs - mean * mean;
            float rstd = rsqrtf(fmaxf(var, 0.f) + 1e-5f);
            #pragma unroll
            for (int e = 0; e < 8; e++)
                xs[e] = (xs[e] - mean) * rstd * __ldg(gng + k + e) + __ldg(gnb + k + e);
        }
        uint4 hv, lv;
        split2(xs[0], xs[1], hv.x, lv.x);
        split2(xs[2], xs[3], hv.y, lv.y);
        split2(xs[4], xs[5], hv.z, lv.z);
        split2(xs[6], xs[7], hv.w, lv.w);
        *(uint4*)(buf + soffA)        = hv;
        *(uint4*)(buf + 4096 + soffA) = lv;

        uint4 hw, lw;
        split2(rw[0].x, rw[0].y, hw.x, lw.x);
        split2(rw[0].z, rw[0].w, hw.y, lw.y);
        split2(rw[1].x, rw[1].y, hw.z, lw.z);
        split2(rw[1].z, rw[1].w, hw.w, lw.w);
        *(uint4*)(buf + 8192 + soffW0)  = hw;
        *(uint4*)(buf + 16384 + soffW0) = lw;
        split2(rw[2].x, rw[2].y, hw.x, lw.x);
        split2(rw[2].z, rw[2].w, hw.y, lw.y);
        split2(rw[3].x, rw[3].y, hw.z, lw.z);
        split2(rw[3].z, rw[3].w, hw.w, lw.w);
        *(uint4*)(buf + 8192 + soffW1)  = hw;
        *(uint4*)(buf + 16384 + soffW1) = lw;
    };
    auto load_regs = [&](int cc) {
        int kb = cc * 32;
        ra[0] = ldcg4(Arow + kb);
        ra[1] = ldcg4(Arow + kb + 4);
        rw[0] = __ldg((const float4*)(Wrow + kb));
        rw[1] = __ldg((const float4*)(Wrow + kb + 4));
        rw[2] = __ldg((const float4*)(Wrow + kb + 8));
        rw[3] = __ldg((const float4*)(Wrow + kb + 12));
    };

    load_regs(0);
    convert_to(sm, 0);
    load_regs(1);
    __syncthreads();

    for (int c = 0; c < nch; c++) {
        // grab one copy ticket for this chunk (double-buffered broadcast slot)
        if (tid == 0) s_t2[c & 1] = atomicAdd(&g_ticket, 1);

        if (c + 1 < nch) {
            convert_to(sm + ((c + 1) % 3) * BUFB, c + 1);
            if (c + 2 < nch) load_regs(c + 2);
        }
        uint32_t bu = sb + (c % 3) * BUFB;
        #pragma unroll
        for (int ks = 0; ks < 2; ks++) {
            uint32_t ah[2][4], al[2][4], bh[4][2], bl[4][2];
            #pragma unroll
            for (int mt = 0; mt < 2; mt++) {
                uint32_t off = (uint32_t)(mbase + mt * 16 + (lane & 15)) * 64
                             + ks * 32 + (lane >> 4) * 16;
                ldsm4(ah[mt], bu + swz64(off));
                ldsm4(al[mt], bu + 4096 + swz64(off));
            }
            #pragma unroll
            for (int nt = 0; nt < 4; nt++) {
                uint32_t off = (uint32_t)(nbase + nt * 8 + (lane & 7)) * 64
                             + ks * 32 + ((lane >> 3) & 1) * 16;
                ldsm2(bh[nt], bu + 8192 + swz64(off));
                ldsm2(bl[nt], bu + 16384 + swz64(off));
            }
            #pragma unroll
            for (int mt = 0; mt < 2; mt++)
                #pragma unroll
                for (int nt = 0; nt < 4; nt++) {
                    mma16816(acc[mt][nt], ah[mt], bh[nt]);
                    mma16816(acc[mt][nt], al[mt], bh[nt]);
                    mma16816(acc[mt][nt], ah[mt], bl[nt]);
                }
        }
        __syncthreads();
        // overlapped copy for this chunk's ticket (fills MMA/LDG stall slots)
        copy_slot(pp, (long)s_t2[c & 1]);
    }

    // secondary publishes its partial before the rendezvous
    if (!primary) {
        #pragma unroll
        for (int mt = 0; mt < 2; mt++)
            #pragma unroll
            for (int nt = 0; nt < 4; nt++) {
                int cl = nbase + nt * 8 + (lane & 3) * 2;
                #pragma unroll
                for (int h = 0; h < 2; h++) {
                    int r = mbase + mt * 16 + (lane >> 2) + h * 8;
                    float2 v = {acc[mt][nt][h * 2], acc[mt][nt][h * 2 + 1]};
                    *(float2*)(part + r * 128 + cl) = v;
                }
            }
    }

    barrier_on(mbar, 2);
    if (!primary) return;

    #pragma unroll
    for (int mt = 0; mt < 2; mt++)
        #pragma unroll
        for (int nt = 0; nt < 4; nt++) {
            int cl = nbase + nt * 8 + (lane & 3) * 2;
            int cc = n0 + cl;
            int gblk = ((n0 + nbase + nt * 8) * magic) >> 16;
            #pragma unroll
            for (int h = 0; h < 2; h++) {
                int r = mbase + mt * 16 + (lane >> 2) + h * 8;
                float2 pv = ldcg2(part + r * 128 + cl);
                float v0 = acc[mt][nt][h * 2 + 0] + pv.x + __ldg(bias + cc);
                float v1 = acc[mt][nt][h * 2 + 1] + pv.y + __ldg(bias + cc + 1);
                if (MODE <= 1) {
                    v0 = v0 / (1.f + __expf(-v0));
                    v1 = v1 / (1.f + __expf(-v1));
                }
                if (MODE == 1) {
                    float2 rv = ldcg2(A + (size_t)r * hid + cc);
                    v0 += rv.x; v1 += rv.y;
                }
                float2 o2 = {v0, v1};
                *(float2*)(O + (size_t)r * hid + cc) = o2;
                if (STATS) {
                    float ps = v0 + v1;
                    float q = v0 * v0 + v1 * v1;
                    ps += __shfl_xor_sync(0xffffffff, ps, 1);
                    q  += __shfl_xor_sync(0xffffffff, q, 1);
                    ps += __shfl_xor_sync(0xffffffff, ps, 2);
                    q  += __shfl_xor_sync(0xffffffff, q, 2);
                    if ((lane & 3) == 0) {
                        atomicAdd(ws_s + r * 32 + gblk, ps);
                        atomicAdd(ws_q + r * 32 + gblk, q);
                    }
                }
            }
        }
}

// ---------------- ticketed copy (dedicated CTAs + post-compute drain) ----------------
__device__ void copy_work(const Params& p, int* s_ticket) {
    while (true) {
        if (threadIdx.x == 0) *s_ticket = atomicAdd(&g_ticket, 4);
        __syncthreads();
        long t0 = *s_ticket;
        __syncthreads();
        if (t0 * SLOT4 >= N4T) break;
        #pragma unroll
        for (int j = 0; j < 4; j++)
            copy_slot(p, t0 + j);
    }
}

// ---------------- scatter ----------------
__device__ void scatter_all(float* __restrict__ out, int cid) {
    for (int c = cid; c < 80; c += NCTA) {
        int te = c / 40, rem = c % 40, b = rem / 5, r = rem % 5;
        int np = g_npos[b];
        if (!np) continue;
        int hid = te ? H2C : H1C;
        int t = (r < 4) ? r : 3;
        int chain = te * 4 + t;
        const float* tok = g_bufA + ch_off(chain);
        float* o = te ? out + OUT0_ELEMS + (size_t)b * SSV * H2C
                      : out + (size_t)b * SSV * H1C;
        int h4 = hid >> 2, tot = np * h4;
        for (int e = threadIdx.x; e < tot; e += NTHR) {
            int i = e / h4, c4 = e % h4;
            int s = (r < 4) ? (SSV - 1 - r * np - i) : (SSV - 5 * np + i);
            float4 v = __ldcg((const float4*)(tok + (size_t)(b * 16 + i) * hid) + c4);
            ((float4*)(o + (size_t)s * hid))[c4] = v;
        }
    }
}

// ---------------- kernels ----------------
__global__ void reset_kernel() {
    int idx = blockIdx.x * 256 + threadIdx.x;
    if (idx < 3 * 8 * 4096) { g_sum[idx] = 0.f; g_ss[idx] = 0.f; }
    if (idx < 640) g_mbar[idx] = 0;
    if (idx < 40) g_cbar[idx] = 0;
    if (idx == 40) { g_gbar = 0; g_ticket = 0; }
}

__global__ void __launch_bounds__(NTHR, 2) mega_kernel(Params p) {
    extern __shared__ char smraw[];
    __shared__ int s_ticket;
    __shared__ int s_t2[2];
    int cid = blockIdx.x, tid = threadIdx.x;

    if (cid >= NCOMP) {
        copy_work(p, &s_ticket);
        barrier_on(&g_gbar, NCTA);
        scatter_all(p.out, cid);
        return;
    }

    uint32_t sb0 = s2u(smraw);
    uint32_t sb = (sb0 + 1023) & ~1023u;
    char* sm = smraw + (sb - sb0);
    int lane = tid & 31, wid = tid >> 5;

    if (cid < 8 && wid == 0) {
        int b = cid, cnt = 0;
        for (int s = 0; s < 16; s++) {
            float v = 0.f;
            #pragma unroll
            for (int j = 0; j < 8; j++)
                v += fabsf(p.extra[((size_t)b * 16 + s) * 704 + 448 + lane * 8 + j]);
            #pragma unroll
            for (int o = 16; o > 0; o >>= 1)
                v += __shfl_xor_sync(0xffffffff, v, o);
            if (v > 1e-6f) cnt++;
        }
        if (lane == 0) g_npos[b] = cnt;
    }

    // decode: cid<160: te2 chains (4 x 40: kh x mt x nt = 2x2x10)
    //         160<=cid<256: te1 chains (4 x 24: 2x2x6)
    int chain, nt, mt, kh, hid, nc_chain, slot;
    if (cid < 160) {
        chain = 4 + cid / 40;
        int r = cid % 40;
        kh = r / 20; int rr = r % 20;
        mt = rr / 10; nt = rr % 10;
        hid = 1280; nc_chain = 40;
        slot = 48 + (chain - 4) * 20 + mt * 10 + nt;
    } else {
        int c2 = cid - 160;
        chain = c2 / 24;
        int r = c2 % 24;
        kh = r / 12; int rr = r % 12;
        mt = rr / 6; nt = rr % 6;
        hid = 768; nc_chain = 24;
        slot = chain * 12 + mt * 6 + nt;
    }
    int te = chain >> 2, t = chain & 3;
    int n0 = nt * 64, m0 = mt * 64;
    n0 = nt * 64;  // (R9 used nt*64? no: R9 tile N=128 -> n0 = nt*... see below)
    // R9 mapping: N-tile width 128? No — R9 warp layout covers N=128 via nbase (wid>>1)*32.
    // R9 used n0 = nt * 128 with 10 nt for hid=1280? 10*128=1280 ✓, 6*128=768 ✓.
    n0 = nt * 128;
    int magic = (hid == 768) ? 2731 : 1639;
    float inv_gs = 1.f / (float)(hid >> 5);
    size_t co = ch_off(chain);
    bool primary = (kh == 0);
    float* part = g_part + (size_t)slot * 8192;
    int* mb = g_mbar + slot * 5;
    int* cb = g_cbar + chain * 5;

    float* st_s0 = g_sum + (0 * 8 + chain) * 4096 + m0 * 32;
    float* st_q0 = g_ss  + (0 * 8 + chain) * 4096 + m0 * 32;
    float* st_s1 = g_sum + (1 * 8 + chain) * 4096 + m0 * 32;
    float* st_q1 = g_ss  + (1 * 8 + chain) * 4096 + m0 * 32;
    float* st_s2 = g_sum + (2 * 8 + chain) * 4096 + m0 * 32;
    float* st_q2 = g_ss  + (2 * 8 + chain) * 4096 + m0 * 32;

    int Kh_fc1 = 352, Kh = hid >> 1;
    float* bA = g_bufA + co + (size_t)m0 * hid;
    float* bB = g_bufB + co + (size_t)m0 * hid;

    run_stage<0, true>(sm, sb, p.extra + (size_t)m0 * 704, bA,
                       p.f1w[te] + (size_t)t * hid * 704, p.f1b[te] + t * hid,
                       nullptr, nullptr, nullptr, nullptr, st_s0, st_q0,
                       704, Kh_fc1, kh * Kh_fc1, hid, n0, magic, inv_gs,
                       part, mb + 0, primary, p, s_t2);
    barrier_on(cb + 0, nc_chain);

    {
        size_t wo = (size_t)(t * 3 + 0) * hid;
        run_stage<1, true>(sm, sb, bA, bB,
                           p.bw[te] + wo * hid, p.bb[te] + wo,
                           p.gg[te] + wo, p.gb[te] + wo, st_s0, st_q0, st_s1, st_q1,
                           hid, Kh, kh * Kh, hid, n0, magic, inv_gs,
                           part, mb + 1, primary, p, s_t2);
    }
    barrier_on(cb + 1, nc_chain);

    {
        size_t wo = (size_t)(t * 3 + 1) * hid;
        run_stage<1, true>(sm, sb, bB, bA,
                           p.bw[te] + wo * hid, p.bb[te] + wo,
                           p.gg[te] + wo, p.gb[te] + wo, st_s1, st_q1, st_s2, st_q2,
                           hid, Kh, kh * Kh, hid, n0, magic, inv_gs,
                           part, mb + 2, primary, p, s_t2);
    }
    barrier_on(cb + 2, nc_chain);

    {
        size_t wo = (size_t)(t * 3 + 2) * hid;
        run_stage<1, false>(sm, sb, bA, bB,
                            p.bw[te] + wo * hid, p.bb[te] + wo,
                            p.gg[te] + wo, p.gb[te] + wo, st_s2, st_q2, nullptr, nullptr,
                            hid, Kh, kh * Kh, hid, n0, magic, inv_gs,
                            part, mb + 3, primary, p, s_t2);
    }
    barrier_on(cb + 3, nc_chain);

    run_stage<2, false>(sm, sb, bB, bA,
                        p.ow[te] + (size_t)t * hid * hid, p.ob[te] + t * hid,
                        nullptr, nullptr, nullptr, nullptr, nullptr, nullptr,
                        hid, Kh, kh * Kh, hid, n0, magic, inv_gs,
                        part, mb + 4, primary, p, s_t2);

    copy_work(p, &s_ticket);
    barrier_on(&g_gbar, NCTA);
    scatter_all(p.out, cid);
}

// ---------------- launch ----------------
extern "C" void kernel_launch(void* const* d_in, const int* in_sizes, int n_in,
                              void* d_out, int out_size) {
    Params p;
    p.e0    = (const float*)d_in[0];
    p.e1    = (const float*)d_in[1];
    p.e2    = (const float*)d_in[2];
    p.extra = (const float*)d_in[3];
    p.f1w[0] = (const float*)d_in[4];  p.f1b[0] = (const float*)d_in[5];
    p.gg[0]  = (const float*)d_in[6];  p.gb[0]  = (const float*)d_in[7];
    p.bw[0]  = (const float*)d_in[8];  p.bb[0]  = (const float*)d_in[9];
    p.ow[0]  = (const float*)d_in[10]; p.ob[0]  = (const float*)d_in[11];
    p.f1w[1] = (const float*)d_in[12]; p.f1b[1] = (const float*)d_in[13];
    p.gg[1]  = (const float*)d_in[14]; p.gb[1]  = (const float*)d_in[15];
    p.bw[1]  = (const float*)d_in[16]; p.bb[1]  = (const float*)d_in[17];
    p.ow[1]  = (const float*)d_in[18]; p.ob[1]  = (const float*)d_in[19];
    p.out = (float*)d_out;

    cudaFuncSetAttribute(mega_kernel, cudaFuncAttributeMaxDynamicSharedMemorySize, SMEM_BYTES);

    reset_kernel<<<(3 * 8 * 4096 + 255) / 256, 256>>>();
    mega_kernel<<<NCTA, NTHR, SMEM_BYTES>>>(p);
}